// round 1
// baseline (speedup 1.0000x reference)
#include <cuda_runtime.h>
#include <math.h>

#define Bc 2
#define Sc 1024
#define Mc 1024
#define Dc 1024
#define Hc 16
#define DHc 64
#define Kc 2048
#define Rc 4095
#define HDc 1024

// -------- scratch (static device globals; allocation is forbidden) --------
__device__ float g_cln[Bc * Kc * Dc];    // LN(concat(memory,hidden)); rows [b*K+M, b*K+K) == h_ln
__device__ float g_q[Bc * Sc * HDc];     // (b, s, h*64+d)
__device__ float g_k[Bc * Kc * HDc];
__device__ float g_v[Bc * Kc * HDc];
__device__ float g_attn[Bc * Sc * HDc];  // attention output before Wo

// ---------------------------------------------------------------------------
// LayerNorm over rows of concat(memory, hidden): row = b*K + r
// ---------------------------------------------------------------------------
__global__ void ln_kernel(const float* __restrict__ hidden,
                          const float* __restrict__ memory,
                          const float* __restrict__ gamma,
                          const float* __restrict__ beta) {
    int row = blockIdx.x;
    int b = row / Kc, r = row % Kc;
    const float* src = (r < Mc) ? (memory + ((size_t)b * Mc + r) * Dc)
                                : (hidden + ((size_t)b * Sc + (r - Mc)) * Dc);
    int t = threadIdx.x;
    float x[4];
    float s = 0.f, sq = 0.f;
#pragma unroll
    for (int i = 0; i < 4; i++) {
        x[i] = src[t + 256 * i];
        s += x[i];
        sq += x[i] * x[i];
    }
#pragma unroll
    for (int m = 16; m; m >>= 1) {
        s  += __shfl_xor_sync(0xffffffffu, s, m);
        sq += __shfl_xor_sync(0xffffffffu, sq, m);
    }
    __shared__ float ss[8], ssq[8];
    int w = t >> 5, l = t & 31;
    if (l == 0) { ss[w] = s; ssq[w] = sq; }
    __syncthreads();
    if (w == 0) {
        float sv  = (l < 8) ? ss[l]  : 0.f;
        float sqv = (l < 8) ? ssq[l] : 0.f;
#pragma unroll
        for (int m = 4; m; m >>= 1) {
            sv  += __shfl_xor_sync(0xffffffffu, sv, m);
            sqv += __shfl_xor_sync(0xffffffffu, sqv, m);
        }
        if (l == 0) { ss[0] = sv; ssq[0] = sqv; }
    }
    __syncthreads();
    float mean = ss[0] * (1.f / Dc);
    float var  = ssq[0] * (1.f / Dc) - mean * mean;
    float inv  = rsqrtf(var + 1e-5f);
    float* dst = g_cln + (size_t)row * Dc;
#pragma unroll
    for (int i = 0; i < 4; i++) {
        int d = t + 256 * i;
        dst[d] = (x[i] - mean) * inv * gamma[d] + beta[d];
    }
}

// ---------------------------------------------------------------------------
// Tiled fp32 GEMM: C[rows x N] = A[rows x Kd] @ W[Kd x N]
// 128x128 tile, 256 threads, 8x8 micro (scattered mapping -> conflict-free LDS)
// addmode==1: C += h_ln (row over B*S maps into g_cln)
// ---------------------------------------------------------------------------
__global__ void gemm_kernel(const float* __restrict__ A,
                            const float* __restrict__ W,
                            float* __restrict__ C,
                            int Kd, int N, int addmode) {
    __shared__ float As[8][132];
    __shared__ float Bs[8][132];
    int t = threadIdx.x, tx = t & 15, ty = t >> 4;
    int row0 = blockIdx.y * 128, col0 = blockIdx.x * 128;
    float acc[8][8] = {};
    for (int k0 = 0; k0 < Kd; k0 += 8) {
        __syncthreads();
#pragma unroll
        for (int e = t; e < 1024; e += 256) {
            int r = e >> 3, kk = e & 7;
            As[kk][r] = A[(size_t)(row0 + r) * Kd + k0 + kk];
        }
#pragma unroll
        for (int e = t; e < 1024; e += 256) {
            int kk = e >> 7, c = e & 127;
            Bs[kk][c] = W[(size_t)(k0 + kk) * N + col0 + c];
        }
        __syncthreads();
#pragma unroll
        for (int kk = 0; kk < 8; kk++) {
            float a[8], bb[8];
#pragma unroll
            for (int i = 0; i < 8; i++) a[i] = As[kk][ty + 16 * i];
#pragma unroll
            for (int j = 0; j < 8; j++) bb[j] = Bs[kk][tx + 16 * j];
#pragma unroll
            for (int i = 0; i < 8; i++)
#pragma unroll
                for (int j = 0; j < 8; j++) acc[i][j] += a[i] * bb[j];
        }
    }
#pragma unroll
    for (int i = 0; i < 8; i++) {
        int row = row0 + ty + 16 * i;
#pragma unroll
        for (int j = 0; j < 8; j++) {
            int col = col0 + tx + 16 * j;
            float v = acc[i][j];
            if (addmode) {
                int b = row / Sc, srow = row % Sc;
                v += g_cln[((size_t)b * Kc + Mc + srow) * Dc + col];
            }
            C[(size_t)row * N + col] = v;
        }
    }
}

// ---------------------------------------------------------------------------
// Flash attention with relative position skew.
// grid: (S/64, B*H), 256 threads. BQ=BK=64, DH=64.
// score[s,k] = (q_s . k_k + q_s . pos[b, k - s + S - 1]) / 32 ; mask k > s+M
// ---------------------------------------------------------------------------
#define ATTN_SMEM_FLOATS (4 * 64 * 65 + 128 * 65 + 64 * 129)
__global__ void attn_kernel(const float* __restrict__ pos_emb) {
    extern __shared__ float sm[];
    float* qs = sm;                 // [64][65]
    float* ks = qs + 64 * 65;       // [64][65]
    float* vs = ks + 64 * 65;       // [64][65]
    float* pb = vs + 64 * 65;       // [64][65]  probs
    float* ps = pb + 64 * 65;       // [128][65] pos band
    float* qp = ps + 128 * 65;      // [64][129] q @ pos^T

    int t = threadIdx.x, tx = t & 15, ty = t >> 4;
    int s0 = blockIdx.x * 64;
    int bh = blockIdx.y;
    int b = bh / Hc, h = bh % Hc;

    for (int e = t; e < 4096; e += 256) {
        int r = e >> 6, d = e & 63;
        qs[r * 65 + d] = g_q[((size_t)b * Sc + s0 + r) * HDc + h * 64 + d];
    }

    float m[4], l[4], O[4][4];
#pragma unroll
    for (int i = 0; i < 4; i++) {
        m[i] = -1e30f; l[i] = 0.f;
#pragma unroll
        for (int j = 0; j < 4; j++) O[i][j] = 0.f;
    }

    int ntiles = s0 / 64 + 17;  // covers keys up to s0+63+M
    for (int kt = 0; kt < ntiles; kt++) {
        int k0 = kt * 64;
        __syncthreads();
        for (int e = t; e < 4096; e += 256) {
            int r = e >> 6, d = e & 63;
            size_t gi = ((size_t)b * Kc + k0 + r) * HDc + h * 64 + d;
            ks[r * 65 + d] = g_k[gi];
            vs[r * 65 + d] = g_v[gi];
        }
        int rr0 = k0 - s0 + Sc - 64;  // pos row for (dq=63, dk=0) ... +127 covers band
        for (int e = t; e < 8192; e += 256) {
            int r = e >> 6, d = e & 63;
            ps[r * 65 + d] = pos_emb[((size_t)b * Rc + rr0 + r) * DHc + d];
        }
        __syncthreads();

        // qpos tile: rows ty+16i, cols tx+16j (128 cols)
        {
            float qa[4][8] = {};
            for (int d = 0; d < 64; d++) {
                float qv[4], pv[8];
#pragma unroll
                for (int i = 0; i < 4; i++) qv[i] = qs[(ty + 16 * i) * 65 + d];
#pragma unroll
                for (int j = 0; j < 8; j++) pv[j] = ps[(tx + 16 * j) * 65 + d];
#pragma unroll
                for (int i = 0; i < 4; i++)
#pragma unroll
                    for (int j = 0; j < 8; j++) qa[i][j] += qv[i] * pv[j];
            }
#pragma unroll
            for (int i = 0; i < 4; i++)
#pragma unroll
                for (int j = 0; j < 8; j++)
                    qp[(ty + 16 * i) * 129 + tx + 16 * j] = qa[i][j];
        }
        __syncthreads();

        // scores
        float sc_[4][4] = {};
        for (int d = 0; d < 64; d++) {
            float qv[4], kv[4];
#pragma unroll
            for (int i = 0; i < 4; i++) qv[i] = qs[(ty + 16 * i) * 65 + d];
#pragma unroll
            for (int j = 0; j < 4; j++) kv[j] = ks[(tx + 16 * j) * 65 + d];
#pragma unroll
            for (int i = 0; i < 4; i++)
#pragma unroll
                for (int j = 0; j < 4; j++) sc_[i][j] += qv[i] * kv[j];
        }
#pragma unroll
        for (int i = 0; i < 4; i++) {
            int dq = ty + 16 * i, sg = s0 + dq;
#pragma unroll
            for (int j = 0; j < 4; j++) {
                int dk = tx + 16 * j, kg = k0 + dk;
                float v = (sc_[i][j] + qp[dq * 129 + dk - dq + 63]) * 0.03125f;
                if (kg > sg + Mc) v = -1e30f;
                sc_[i][j] = v;
            }
        }

        // online softmax (row reduction across the 16 tx lanes, same half-warp)
#pragma unroll
        for (int i = 0; i < 4; i++) {
            float rm = fmaxf(fmaxf(sc_[i][0], sc_[i][1]), fmaxf(sc_[i][2], sc_[i][3]));
#pragma unroll
            for (int mm = 8; mm; mm >>= 1)
                rm = fmaxf(rm, __shfl_xor_sync(0xffffffffu, rm, mm));
            float mn = fmaxf(m[i], rm);
            float alpha = __expf(m[i] - mn);
            float rs = 0.f;
#pragma unroll
            for (int j = 0; j < 4; j++) {
                float p = __expf(sc_[i][j] - mn);
                sc_[i][j] = p;
                rs += p;
            }
#pragma unroll
            for (int mm = 8; mm; mm >>= 1)
                rs += __shfl_xor_sync(0xffffffffu, rs, mm);
            l[i] = l[i] * alpha + rs;
            m[i] = mn;
#pragma unroll
            for (int j = 0; j < 4; j++) O[i][j] *= alpha;
            int dq = ty + 16 * i;
#pragma unroll
            for (int j = 0; j < 4; j++) pb[dq * 65 + tx + 16 * j] = sc_[i][j];
        }
        __syncwarp();

        // O += P @ V
        for (int dk = 0; dk < 64; dk++) {
            float pv4[4], vv[4];
#pragma unroll
            for (int i = 0; i < 4; i++) pv4[i] = pb[(ty + 16 * i) * 65 + dk];
#pragma unroll
            for (int j = 0; j < 4; j++) vv[j] = vs[dk * 65 + tx + 16 * j];
#pragma unroll
            for (int i = 0; i < 4; i++)
#pragma unroll
                for (int j = 0; j < 4; j++) O[i][j] += pv4[i] * vv[j];
        }
    }

#pragma unroll
    for (int i = 0; i < 4; i++) {
        float inv = 1.f / l[i];
        int sg = s0 + ty + 16 * i;
#pragma unroll
        for (int j = 0; j < 4; j++)
            g_attn[((size_t)b * Sc + sg) * HDc + h * 64 + tx + 16 * j] = O[i][j] * inv;
    }
}

// ---------------------------------------------------------------------------
extern "C" void kernel_launch(void* const* d_in, const int* in_sizes, int n_in,
                              void* d_out, int out_size) {
    const float* hidden  = (const float*)d_in[0];
    const float* pos_emb = (const float*)d_in[1];
    const float* memory  = (const float*)d_in[2];
    // d_in[3] = mask (bool) — recomputed analytically inside attn_kernel
    const float* Wq = (const float*)d_in[4];
    const float* Wk = (const float*)d_in[5];
    const float* Wv = (const float*)d_in[6];
    const float* Wo = (const float*)d_in[7];
    const float* gamma = (const float*)d_in[8];
    const float* beta  = (const float*)d_in[9];
    float* out = (float*)d_out;

    float *cln, *q, *k, *v, *attn;
    cudaGetSymbolAddress((void**)&cln,  g_cln);
    cudaGetSymbolAddress((void**)&q,    g_q);
    cudaGetSymbolAddress((void**)&k,    g_k);
    cudaGetSymbolAddress((void**)&v,    g_v);
    cudaGetSymbolAddress((void**)&attn, g_attn);

    // 1. LayerNorm of concat(memory, hidden)
    ln_kernel<<<Bc * Kc, 256>>>(hidden, memory, gamma, beta);

    // 2. Projections
    for (int b = 0; b < Bc; b++) {
        gemm_kernel<<<dim3(HDc / 128, Sc / 128), 256>>>(
            cln + ((size_t)b * Kc + Mc) * Dc, Wq, q + (size_t)b * Sc * HDc,
            Dc, HDc, 0);
    }
    gemm_kernel<<<dim3(HDc / 128, (Bc * Kc) / 128), 256>>>(cln, Wk, k, Dc, HDc, 0);
    gemm_kernel<<<dim3(HDc / 128, (Bc * Kc) / 128), 256>>>(cln, Wv, v, Dc, HDc, 0);

    // 3. Attention
    int smem_bytes = ATTN_SMEM_FLOATS * (int)sizeof(float);
    cudaFuncSetAttribute(attn_kernel, cudaFuncAttributeMaxDynamicSharedMemorySize,
                         smem_bytes);
    attn_kernel<<<dim3(Sc / 64, Bc * Hc), 256, smem_bytes>>>(pos_emb);

    // 4. Output projection + residual h_ln
    gemm_kernel<<<dim3(Dc / 128, (Bc * Sc) / 128), 256>>>(attn, Wo, out, HDc, Dc, 1);
}

// round 2
// speedup vs baseline: 4.5547x; 4.5547x over previous
#include <cuda_runtime.h>
#include <stdint.h>
#include <math.h>

#define Bc 2
#define Sc 1024
#define Mc 1024
#define Dc 1024
#define Hc 16
#define DHc 64
#define Kc 2048
#define Rc 4095
#define HDc 1024

// -------- scratch (static device globals; allocation is forbidden) --------
__device__ float g_cln[Bc * Kc * Dc];
__device__ float g_q[Bc * Sc * HDc];
__device__ float g_k[Bc * Kc * HDc];
__device__ float g_v[Bc * Kc * HDc];
__device__ float g_attn[Bc * Sc * HDc];
__device__ float g_pos[Bc * Rc * DHc];   // tf32-rounded pos_emb

// ---------------------------------------------------------------------------
__device__ __forceinline__ float ftf(float x) {
    uint32_t u; asm("cvt.rna.tf32.f32 %0, %1;" : "=r"(u) : "f"(x));
    return __uint_as_float(u);
}
__device__ __forceinline__ uint32_t sptr(const void* p) {
    return (uint32_t)__cvta_generic_to_shared(p);
}
__device__ __forceinline__ void ldm4(uint32_t* r, uint32_t a) {
    asm volatile("ldmatrix.sync.aligned.m8n8.x4.shared.b16 {%0,%1,%2,%3},[%4];"
                 : "=r"(r[0]), "=r"(r[1]), "=r"(r[2]), "=r"(r[3]) : "r"(a));
}
__device__ __forceinline__ void mma8(float* d, const uint32_t* a,
                                     uint32_t b0, uint32_t b1) {
    asm volatile(
        "mma.sync.aligned.m16n8k8.row.col.f32.tf32.tf32.f32 "
        "{%0,%1,%2,%3},{%4,%5,%6,%7},{%8,%9},{%0,%1,%2,%3};"
        : "+f"(d[0]), "+f"(d[1]), "+f"(d[2]), "+f"(d[3])
        : "r"(a[0]), "r"(a[1]), "r"(a[2]), "r"(a[3]), "r"(b0), "r"(b1));
}

// ---------------------------------------------------------------------------
__global__ void roundpos_kernel(const float* __restrict__ p) {
    int i = blockIdx.x * 256 + threadIdx.x;
    if (i < Bc * Rc * DHc) g_pos[i] = ftf(p[i]);
}

// ---------------------------------------------------------------------------
__global__ void ln_kernel(const float* __restrict__ hidden,
                          const float* __restrict__ memory,
                          const float* __restrict__ gamma,
                          const float* __restrict__ beta) {
    int row = blockIdx.x;
    int b = row / Kc, r = row % Kc;
    const float* src = (r < Mc) ? (memory + ((size_t)b * Mc + r) * Dc)
                                : (hidden + ((size_t)b * Sc + (r - Mc)) * Dc);
    int t = threadIdx.x;
    float x[4];
    float s = 0.f, sq = 0.f;
#pragma unroll
    for (int i = 0; i < 4; i++) {
        x[i] = src[t + 256 * i];
        s += x[i];
        sq += x[i] * x[i];
    }
#pragma unroll
    for (int m = 16; m; m >>= 1) {
        s  += __shfl_xor_sync(0xffffffffu, s, m);
        sq += __shfl_xor_sync(0xffffffffu, sq, m);
    }
    __shared__ float ss[8], ssq[8];
    int w = t >> 5, l = t & 31;
    if (l == 0) { ss[w] = s; ssq[w] = sq; }
    __syncthreads();
    if (w == 0) {
        float sv  = (l < 8) ? ss[l]  : 0.f;
        float sqv = (l < 8) ? ssq[l] : 0.f;
#pragma unroll
        for (int m = 4; m; m >>= 1) {
            sv  += __shfl_xor_sync(0xffffffffu, sv, m);
            sqv += __shfl_xor_sync(0xffffffffu, sqv, m);
        }
        if (l == 0) { ss[0] = sv; ssq[0] = sqv; }
    }
    __syncthreads();
    float mean = ss[0] * (1.f / Dc);
    float var  = ssq[0] * (1.f / Dc) - mean * mean;
    float inv  = rsqrtf(var + 1e-5f);
    float* dst = g_cln + (size_t)row * Dc;
#pragma unroll
    for (int i = 0; i < 4; i++) {
        int d = t + 256 * i;
        dst[d] = (x[i] - mean) * inv * gamma[d] + beta[d];
    }
}

// ---------------------------------------------------------------------------
// Tensor-core tf32 GEMM: C[rows x N] = A[rows x Kd] @ W[Kd x N]
// 128x128 block, 8 warps (4m x 2n), warp tile 32x64.
// mode 1: += h_ln residual (rows map into g_cln); mode 2: tf32-round output.
// ---------------------------------------------------------------------------
__global__ __launch_bounds__(256) void gemm_tc(const float* __restrict__ A,
                                               const float* __restrict__ W,
                                               float* __restrict__ C,
                                               int Kd, int N, int mode) {
    __shared__ __align__(16) float As[128 * 20];
    __shared__ __align__(16) float Bs[16 * 136];
    int t = threadIdx.x, lane = t & 31, w = t >> 5;
    int wm = (w >> 1) << 5, wn = (w & 1) << 6;
    int row0 = blockIdx.y << 7, col0 = blockIdx.x << 7;
    int g = lane >> 3, rr = lane & 7;

    float acc[2][8][4];
#pragma unroll
    for (int mt = 0; mt < 2; mt++)
#pragma unroll
        for (int nt = 0; nt < 8; nt++)
#pragma unroll
            for (int i = 0; i < 4; i++) acc[mt][nt][i] = 0.f;

    for (int k0 = 0; k0 < Kd; k0 += 16) {
        __syncthreads();
#pragma unroll
        for (int it = 0; it < 2; it++) {
            int e = t + it * 256;
            int r = e >> 2, c4 = e & 3;
            float4 v = *(const float4*)(A + (size_t)(row0 + r) * Kd + k0 + (c4 << 2));
            float* d = &As[r * 20 + (c4 << 2)];
            d[0] = ftf(v.x); d[1] = ftf(v.y); d[2] = ftf(v.z); d[3] = ftf(v.w);
        }
#pragma unroll
        for (int it = 0; it < 2; it++) {
            int e = t + it * 256;
            int r = e >> 5, c4 = e & 31;
            float4 v = *(const float4*)(W + (size_t)(k0 + r) * N + col0 + (c4 << 2));
            float* d = &Bs[r * 136 + (c4 << 2)];
            d[0] = ftf(v.x); d[1] = ftf(v.y); d[2] = ftf(v.z); d[3] = ftf(v.w);
        }
        __syncthreads();
#pragma unroll
        for (int kk = 0; kk < 16; kk += 8) {
            uint32_t a[2][4];
#pragma unroll
            for (int mt = 0; mt < 2; mt++)
                ldm4(a[mt], sptr(&As[(wm + mt * 16 + rr + ((g & 1) << 3)) * 20 +
                                     kk + ((g >> 1) << 2)]));
#pragma unroll
            for (int nt = 0; nt < 8; nt++) {
                int n = wn + (nt << 3) + (lane >> 2);
                uint32_t b0 = __float_as_uint(Bs[(kk + (lane & 3)) * 136 + n]);
                uint32_t b1 = __float_as_uint(Bs[(kk + 4 + (lane & 3)) * 136 + n]);
                mma8(acc[0][nt], a[0], b0, b1);
                mma8(acc[1][nt], a[1], b0, b1);
            }
        }
    }

    int rA = row0 + wm + (lane >> 2);
#pragma unroll
    for (int mt = 0; mt < 2; mt++) {
        int r0 = rA + mt * 16, r1 = r0 + 8;
#pragma unroll
        for (int nt = 0; nt < 8; nt++) {
            int c = col0 + wn + (nt << 3) + ((lane & 3) << 1);
            float v0 = acc[mt][nt][0], v1 = acc[mt][nt][1];
            float v2 = acc[mt][nt][2], v3 = acc[mt][nt][3];
            if (mode == 1) {
                int b0r = r0 >> 10, s0r = r0 & 1023;
                int b1r = r1 >> 10, s1r = r1 & 1023;
                const float* rs0 = &g_cln[((size_t)b0r * Kc + Mc + s0r) * Dc + c];
                const float* rs1 = &g_cln[((size_t)b1r * Kc + Mc + s1r) * Dc + c];
                v0 += rs0[0]; v1 += rs0[1];
                v2 += rs1[0]; v3 += rs1[1];
            } else if (mode == 2) {
                v0 = ftf(v0); v1 = ftf(v1); v2 = ftf(v2); v3 = ftf(v3);
            }
            C[(size_t)r0 * N + c] = v0; C[(size_t)r0 * N + c + 1] = v1;
            C[(size_t)r1 * N + c] = v2; C[(size_t)r1 * N + c + 1] = v3;
        }
    }
}

// ---------------------------------------------------------------------------
// Tensor-core flash attention with relative position skew.
// 128 threads (4 warps); warp w owns query rows [w*16, w*16+16).
// score[s,k] = (q.k + q.pos[k-s+S-1]) / 32 ; mask k > s+M.
// ---------------------------------------------------------------------------
#define OFF_V  (64 * 68)
#define OFF_PB (OFF_V + 64 * 72)
#define OFF_QP (OFF_PB + 128 * 68)
#define SM_FLOATS (OFF_QP + 64 * 132)

__global__ __launch_bounds__(128) void attn_tc() {
    extern __shared__ __align__(16) float sm[];
    float* Ks = sm;                // [64][68]   keys, natural [key][dh]
    float* Vs = sm + OFF_V;        // [64][72]   values, natural [key][dh]
    float* Pb = sm + OFF_PB;       // [128][68]  pos band (also Q staging)
    float* Qp = sm + OFF_QP;       // [64][132]  qpos band, reused for P

    int t = threadIdx.x, lane = t & 31, w = t >> 5;
    int g = lane >> 3, rr = lane & 7, R = lane >> 2, c2 = (lane & 3) << 1;
    int qi = 15 - (int)blockIdx.x;          // biggest workloads first
    int s0 = qi << 6;
    int bh = blockIdx.y, b = bh >> 4, h = bh & 15;

    // stage Q (pre-rounded tf32) and load resident A fragments
    const float* qbase = g_q + ((size_t)(b * Sc + s0)) * HDc + h * 64;
    for (int e = t; e < 1024; e += 128) {
        int r = e >> 4, c4 = e & 15;
        *(float4*)&Pb[r * 68 + (c4 << 2)] =
            *(const float4*)(qbase + (size_t)r * HDc + (c4 << 2));
    }
    __syncthreads();
    uint32_t qf[8][4];
#pragma unroll
    for (int k8 = 0; k8 < 8; k8++)
        ldm4(qf[k8], sptr(&Pb[(w * 16 + rr + ((g & 1) << 3)) * 68 +
                              (k8 << 3) + ((g >> 1) << 2)]));

    float O[8][4];
#pragma unroll
    for (int nt = 0; nt < 8; nt++)
#pragma unroll
        for (int i = 0; i < 4; i++) O[nt][i] = 0.f;
    float m0 = -1e30f, m1 = -1e30f, l0 = 0.f, l1 = 0.f;

    const float* kbase = g_k + ((size_t)b * Kc) * HDc + h * 64;
    const float* vbase = g_v + ((size_t)b * Kc) * HDc + h * 64;
    const float* pbase = g_pos + (size_t)b * Rc * DHc;
    int dq0 = w * 16 + R, dq1 = dq0 + 8;
    int ntiles = qi + 17;

    for (int kt = 0; kt < ntiles; kt++) {
        int k0 = kt << 6;
        int rr0 = k0 - s0 + (Sc - 64);
        __syncthreads();
        for (int e = t; e < 1024; e += 128) {
            int r = e >> 4, c4 = e & 15;
            *(float4*)&Ks[r * 68 + (c4 << 2)] =
                *(const float4*)(kbase + (size_t)(k0 + r) * HDc + (c4 << 2));
            *(float4*)&Vs[r * 72 + (c4 << 2)] =
                *(const float4*)(vbase + (size_t)(k0 + r) * HDc + (c4 << 2));
        }
        for (int e = t; e < 2048; e += 128) {
            int r = e >> 4, c4 = e & 15;
            *(float4*)&Pb[r * 68 + (c4 << 2)] =
                *(const float4*)(pbase + (size_t)(rr0 + r) * DHc + (c4 << 2));
        }
        __syncthreads();

        // ---- qpos = Q @ pos_band^T  (64x128), stored to Qp (warp-local rows)
#pragma unroll
        for (int np = 0; np < 8; np++) {
            float qa[2][4] = {{0.f,0.f,0.f,0.f},{0.f,0.f,0.f,0.f}};
#pragma unroll
            for (int k8 = 0; k8 < 8; k8++) {
                uint32_t bb[4];
                ldm4(bb, sptr(&Pb[(np * 16 + rr + ((g >> 1) << 3)) * 68 +
                                  (k8 << 3) + ((g & 1) << 2)]));
                mma8(qa[0], qf[k8], bb[0], bb[1]);
                mma8(qa[1], qf[k8], bb[2], bb[3]);
            }
            float* q0 = &Qp[dq0 * 132 + np * 16];
            float* q1 = &Qp[dq1 * 132 + np * 16];
            q0[c2]     = qa[0][0]; q0[c2 + 1]     = qa[0][1];
            q1[c2]     = qa[0][2]; q1[c2 + 1]     = qa[0][3];
            q0[8 + c2] = qa[1][0]; q0[8 + c2 + 1] = qa[1][1];
            q1[8 + c2] = qa[1][2]; q1[8 + c2 + 1] = qa[1][3];
        }
        __syncwarp();

        // ---- scores = Q @ K^T (64x64)
        float sc[8][4];
#pragma unroll
        for (int nt = 0; nt < 8; nt++)
#pragma unroll
            for (int i = 0; i < 4; i++) sc[nt][i] = 0.f;
#pragma unroll
        for (int np = 0; np < 4; np++) {
#pragma unroll
            for (int k8 = 0; k8 < 8; k8++) {
                uint32_t bb[4];
                ldm4(bb, sptr(&Ks[(np * 16 + rr + ((g >> 1) << 3)) * 68 +
                                  (k8 << 3) + ((g & 1) << 2)]));
                mma8(sc[np * 2],     qf[k8], bb[0], bb[1]);
                mma8(sc[np * 2 + 1], qf[k8], bb[2], bb[3]);
            }
        }

        // ---- skew add + mask
#pragma unroll
        for (int nt = 0; nt < 8; nt++) {
#pragma unroll
            for (int j = 0; j < 2; j++) {
                int dk = (nt << 3) + c2 + j;
                float p0 = Qp[dq0 * 132 + dk - dq0 + 63];
                float p1 = Qp[dq1 * 132 + dk - dq1 + 63];
                bool mk0 = (k0 + dk) > (s0 + dq0 + Mc);
                bool mk1 = (k0 + dk) > (s0 + dq1 + Mc);
                sc[nt][j]     = mk0 ? -1e30f : (sc[nt][j] + p0) * 0.03125f;
                sc[nt][2 + j] = mk1 ? -1e30f : (sc[nt][2 + j] + p1) * 0.03125f;
            }
        }

        // ---- online softmax (quad-local rows)
        float mx0 = -1e30f, mx1 = -1e30f;
#pragma unroll
        for (int nt = 0; nt < 8; nt++) {
            mx0 = fmaxf(mx0, fmaxf(sc[nt][0], sc[nt][1]));
            mx1 = fmaxf(mx1, fmaxf(sc[nt][2], sc[nt][3]));
        }
        mx0 = fmaxf(mx0, __shfl_xor_sync(0xffffffffu, mx0, 1));
        mx0 = fmaxf(mx0, __shfl_xor_sync(0xffffffffu, mx0, 2));
        mx1 = fmaxf(mx1, __shfl_xor_sync(0xffffffffu, mx1, 1));
        mx1 = fmaxf(mx1, __shfl_xor_sync(0xffffffffu, mx1, 2));
        float mn0 = fmaxf(m0, mx0), mn1 = fmaxf(m1, mx1);
        float al0 = __expf(m0 - mn0), al1 = __expf(m1 - mn1);
        m0 = mn0; m1 = mn1;
        float su0 = 0.f, su1 = 0.f;
        __syncwarp();
#pragma unroll
        for (int nt = 0; nt < 8; nt++) {
            float p0 = __expf(sc[nt][0] - mn0), p1 = __expf(sc[nt][1] - mn0);
            float p2 = __expf(sc[nt][2] - mn1), p3 = __expf(sc[nt][3] - mn1);
            su0 += p0 + p1; su1 += p2 + p3;
            int dk = (nt << 3) + c2;
            Qp[dq0 * 132 + dk] = ftf(p0); Qp[dq0 * 132 + dk + 1] = ftf(p1);
            Qp[dq1 * 132 + dk] = ftf(p2); Qp[dq1 * 132 + dk + 1] = ftf(p3);
        }
        su0 += __shfl_xor_sync(0xffffffffu, su0, 1);
        su0 += __shfl_xor_sync(0xffffffffu, su0, 2);
        su1 += __shfl_xor_sync(0xffffffffu, su1, 1);
        su1 += __shfl_xor_sync(0xffffffffu, su1, 2);
        l0 = l0 * al0 + su0; l1 = l1 * al1 + su1;
#pragma unroll
        for (int nt = 0; nt < 8; nt++) {
            O[nt][0] *= al0; O[nt][1] *= al0;
            O[nt][2] *= al1; O[nt][3] *= al1;
        }
        __syncwarp();

        // ---- O += P @ V
#pragma unroll
        for (int k8 = 0; k8 < 8; k8++) {
            uint32_t pa[4];
            ldm4(pa, sptr(&Qp[(w * 16 + rr + ((g & 1) << 3)) * 132 +
                              (k8 << 3) + ((g >> 1) << 2)]));
#pragma unroll
            for (int nt = 0; nt < 8; nt++) {
                int n = (nt << 3) + (lane >> 2);
                uint32_t b0 = __float_as_uint(Vs[((k8 << 3) + (lane & 3)) * 72 + n]);
                uint32_t b1 = __float_as_uint(Vs[((k8 << 3) + 4 + (lane & 3)) * 72 + n]);
                mma8(O[nt], pa, b0, b1);
            }
        }
    }

    float i0 = 1.f / l0, i1 = 1.f / l1;
    float* obase = g_attn + ((size_t)(b * Sc + s0)) * HDc + h * 64;
#pragma unroll
    for (int nt = 0; nt < 8; nt++) {
        int c = (nt << 3) + c2;
        obase[(size_t)dq0 * HDc + c]     = O[nt][0] * i0;
        obase[(size_t)dq0 * HDc + c + 1] = O[nt][1] * i0;
        obase[(size_t)dq1 * HDc + c]     = O[nt][2] * i1;
        obase[(size_t)dq1 * HDc + c + 1] = O[nt][3] * i1;
    }
}

// ---------------------------------------------------------------------------
extern "C" void kernel_launch(void* const* d_in, const int* in_sizes, int n_in,
                              void* d_out, int out_size) {
    const float* hidden  = (const float*)d_in[0];
    const float* pos_emb = (const float*)d_in[1];
    const float* memory  = (const float*)d_in[2];
    // d_in[3] = mask (bool) — recomputed analytically
    const float* Wq = (const float*)d_in[4];
    const float* Wk = (const float*)d_in[5];
    const float* Wv = (const float*)d_in[6];
    const float* Wo = (const float*)d_in[7];
    const float* gamma = (const float*)d_in[8];
    const float* beta  = (const float*)d_in[9];
    float* out = (float*)d_out;

    float *cln, *q, *k, *v, *attn;
    cudaGetSymbolAddress((void**)&cln,  g_cln);
    cudaGetSymbolAddress((void**)&q,    g_q);
    cudaGetSymbolAddress((void**)&k,    g_k);
    cudaGetSymbolAddress((void**)&v,    g_v);
    cudaGetSymbolAddress((void**)&attn, g_attn);

    roundpos_kernel<<<(Bc * Rc * DHc + 255) / 256, 256>>>(pos_emb);
    ln_kernel<<<Bc * Kc, 256>>>(hidden, memory, gamma, beta);

    for (int b = 0; b < Bc; b++) {
        gemm_tc<<<dim3(HDc / 128, Sc / 128), 256>>>(
            cln + ((size_t)b * Kc + Mc) * Dc, Wq, q + (size_t)b * Sc * HDc,
            Dc, HDc, 2);
    }
    gemm_tc<<<dim3(HDc / 128, (Bc * Kc) / 128), 256>>>(cln, Wk, k, Dc, HDc, 2);
    gemm_tc<<<dim3(HDc / 128, (Bc * Kc) / 128), 256>>>(cln, Wv, v, Dc, HDc, 2);

    int smem_bytes = SM_FLOATS * (int)sizeof(float);
    cudaFuncSetAttribute(attn_tc, cudaFuncAttributeMaxDynamicSharedMemorySize,
                         smem_bytes);
    attn_tc<<<dim3(Sc / 64, Bc * Hc), 128, smem_bytes>>>();

    gemm_tc<<<dim3(Dc / 128, (Bc * Sc) / 128), 256>>>(attn, Wo, out, HDc, Dc, 1);
}

// round 4
// speedup vs baseline: 6.4330x; 1.4124x over previous
#include <cuda_runtime.h>
#include <stdint.h>
#include <math.h>

#define Bc 2
#define Sc 1024
#define Mc 1024
#define Dc 1024
#define Hc 16
#define DHc 64
#define Kc 2048
#define Rc 4095
#define HDc 1024

// -------- scratch (static device globals; allocation is forbidden) --------
__device__ float g_cln[Bc * Kc * Dc];
__device__ float g_q[Bc * Sc * HDc];
__device__ float g_k[Bc * Kc * HDc];
__device__ float g_v[Bc * Kc * HDc];
__device__ float g_attn[Bc * Sc * HDc];

// ---------------------------------------------------------------------------
__device__ __forceinline__ uint32_t sptr(const void* p) {
    return (uint32_t)__cvta_generic_to_shared(p);
}
__device__ __forceinline__ void ldm4(uint32_t* r, uint32_t a) {
    asm volatile("ldmatrix.sync.aligned.m8n8.x4.shared.b16 {%0,%1,%2,%3},[%4];"
                 : "=r"(r[0]), "=r"(r[1]), "=r"(r[2]), "=r"(r[3]) : "r"(a));
}
__device__ __forceinline__ void mma8(float* d, const uint32_t* a,
                                     uint32_t b0, uint32_t b1) {
    asm volatile(
        "mma.sync.aligned.m16n8k8.row.col.f32.tf32.tf32.f32 "
        "{%0,%1,%2,%3},{%4,%5,%6,%7},{%8,%9},{%0,%1,%2,%3};"
        : "+f"(d[0]), "+f"(d[1]), "+f"(d[2]), "+f"(d[3])
        : "r"(a[0]), "r"(a[1]), "r"(a[2]), "r"(a[3]), "r"(b0), "r"(b1));
}
__device__ __forceinline__ void cpa(uint32_t d, const void* s) {
    asm volatile("cp.async.cg.shared.global [%0], [%1], 16;" :: "r"(d), "l"(s));
}
#define CP_COMMIT asm volatile("cp.async.commit_group;")
#define CP_WAIT(n) asm volatile("cp.async.wait_group %0;" :: "n"(n))

// ---------------------------------------------------------------------------
__global__ void ln_kernel(const float* __restrict__ hidden,
                          const float* __restrict__ memory,
                          const float* __restrict__ gamma,
                          const float* __restrict__ beta) {
    int row = blockIdx.x;
    int b = row / Kc, r = row % Kc;
    const float* src = (r < Mc) ? (memory + ((size_t)b * Mc + r) * Dc)
                                : (hidden + ((size_t)b * Sc + (r - Mc)) * Dc);
    int t = threadIdx.x;
    float x[4];
    float s = 0.f, sq = 0.f;
#pragma unroll
    for (int i = 0; i < 4; i++) {
        x[i] = src[t + 256 * i];
        s += x[i];
        sq += x[i] * x[i];
    }
#pragma unroll
    for (int m = 16; m; m >>= 1) {
        s  += __shfl_xor_sync(0xffffffffu, s, m);
        sq += __shfl_xor_sync(0xffffffffu, sq, m);
    }
    __shared__ float ss[8], ssq[8];
    int w = t >> 5, l = t & 31;
    if (l == 0) { ss[w] = s; ssq[w] = sq; }
    __syncthreads();
    if (w == 0) {
        float sv  = (l < 8) ? ss[l]  : 0.f;
        float sqv = (l < 8) ? ssq[l] : 0.f;
#pragma unroll
        for (int m = 4; m; m >>= 1) {
            sv  += __shfl_xor_sync(0xffffffffu, sv, m);
            sqv += __shfl_xor_sync(0xffffffffu, sqv, m);
        }
        if (l == 0) { ss[0] = sv; ssq[0] = sqv; }
    }
    __syncthreads();
    float mean = ss[0] * (1.f / Dc);
    float var  = ssq[0] * (1.f / Dc) - mean * mean;
    float inv  = rsqrtf(var + 1e-5f);
    float* dst = g_cln + (size_t)row * Dc;
#pragma unroll
    for (int i = 0; i < 4; i++) {
        int d = t + 256 * i;
        dst[d] = (x[i] - mean) * inv * gamma[d] + beta[d];
    }
}

// ---------------------------------------------------------------------------
// Pipelined tf32 GEMM body: C128x128 = A[128x1024] @ W[1024x128] (+residual)
// 8 warps (4m x 2n), 4-stage cp.async pipeline, BK=16.
// ---------------------------------------------------------------------------
#define ASZ (128 * 20)
#define BSZ (16 * 136)
#define STGF (ASZ + BSZ)
#define GEMM_SMEM_BYTES (4 * STGF * 4)

template <bool RES>
__device__ __forceinline__ void gemm_body(const float* __restrict__ A,
                                          const float* __restrict__ W,
                                          float* __restrict__ C,
                                          const float* __restrict__ res,
                                          float* sm) {
    int t = threadIdx.x, lane = t & 31, w = t >> 5;
    int wm = (w >> 1) << 5, wn = (w & 1) << 6;
    int g = lane >> 3, rr = lane & 7;

    auto load_stage = [&](int ki) {
        float* As = sm + (ki & 3) * STGF;
        float* Bs = As + ASZ;
        int k0 = ki << 4;
#pragma unroll
        for (int it = 0; it < 2; it++) {
            int c = t + (it << 8);
            int r = c >> 2, qd = c & 3;
            cpa(sptr(As + r * 20 + (qd << 2)),
                A + (size_t)r * 1024 + k0 + (qd << 2));
        }
#pragma unroll
        for (int it = 0; it < 2; it++) {
            int c = t + (it << 8);
            int r = c >> 5, qd = c & 31;
            cpa(sptr(Bs + r * 136 + (qd << 2)),
                W + (size_t)(k0 + r) * 1024 + (qd << 2));
        }
    };

#pragma unroll
    for (int s = 0; s < 3; s++) { load_stage(s); CP_COMMIT; }

    float acc[2][8][4];
#pragma unroll
    for (int mt = 0; mt < 2; mt++)
#pragma unroll
        for (int nt = 0; nt < 8; nt++)
#pragma unroll
            for (int i = 0; i < 4; i++) acc[mt][nt][i] = 0.f;

    for (int i = 0; i < 64; i++) {
        CP_WAIT(2);
        __syncthreads();
        float* As = sm + (i & 3) * STGF;
        float* Bs = As + ASZ;
#pragma unroll
        for (int kk = 0; kk < 16; kk += 8) {
            uint32_t a0[4], a1[4];
            ldm4(a0, sptr(&As[(wm + rr + ((g & 1) << 3)) * 20 +
                              kk + ((g >> 1) << 2)]));
            ldm4(a1, sptr(&As[(wm + 16 + rr + ((g & 1) << 3)) * 20 +
                              kk + ((g >> 1) << 2)]));
#pragma unroll
            for (int nt = 0; nt < 8; nt++) {
                int n = wn + (nt << 3) + (lane >> 2);
                uint32_t b0 = __float_as_uint(Bs[(kk + (lane & 3)) * 136 + n]);
                uint32_t b1 = __float_as_uint(Bs[(kk + 4 + (lane & 3)) * 136 + n]);
                mma8(acc[0][nt], a0, b0, b1);
                mma8(acc[1][nt], a1, b0, b1);
            }
        }
        __syncthreads();
        if (i + 3 < 64) load_stage(i + 3);
        CP_COMMIT;
    }

    int rA = wm + (lane >> 2);
#pragma unroll
    for (int mt = 0; mt < 2; mt++) {
        int r0 = rA + mt * 16, r1 = r0 + 8;
#pragma unroll
        for (int nt = 0; nt < 8; nt++) {
            int c = wn + (nt << 3) + ((lane & 3) << 1);
            float v0 = acc[mt][nt][0], v1 = acc[mt][nt][1];
            float v2 = acc[mt][nt][2], v3 = acc[mt][nt][3];
            if (RES) {
                const float* rs0 = res + (size_t)r0 * 1024 + c;
                const float* rs1 = res + (size_t)r1 * 1024 + c;
                v0 += rs0[0]; v1 += rs0[1];
                v2 += rs1[0]; v3 += rs1[1];
            }
            C[(size_t)r0 * 1024 + c] = v0; C[(size_t)r0 * 1024 + c + 1] = v1;
            C[(size_t)r1 * 1024 + c] = v2; C[(size_t)r1 * 1024 + c + 1] = v3;
        }
    }
}

// Fused Q/K/V projection: grid (8, 32, 3); z: 0=K, 1=V, 2=Q (y<16)
__global__ __launch_bounds__(256, 2) void proj_tc(const float* __restrict__ Wq,
                                                  const float* __restrict__ Wk,
                                                  const float* __restrict__ Wv) {
    extern __shared__ __align__(16) float sm[];
    int task = blockIdx.z, y = blockIdx.y, col0 = blockIdx.x << 7;
    const float* A;
    const float* W;
    float* Cb;
    if (task == 0) {
        A = g_cln + (size_t)(y << 7) * 1024; W = Wk;
        Cb = g_k + (size_t)(y << 7) * 1024 + col0;
    } else if (task == 1) {
        A = g_cln + (size_t)(y << 7) * 1024; W = Wv;
        Cb = g_v + (size_t)(y << 7) * 1024 + col0;
    } else {
        if (y >= 16) return;
        int b = y >> 3, r0 = (y & 7) << 7;
        A = g_cln + ((size_t)(b * Kc + Mc) + r0) * 1024; W = Wq;
        Cb = g_q + ((size_t)(b * Sc) + r0) * 1024 + col0;
    }
    gemm_body<false>(A, W + col0, Cb, nullptr, sm);
}

// Output projection + residual: grid (8, 16)
__global__ __launch_bounds__(256, 2) void out_tc(const float* __restrict__ Wo,
                                                 float* __restrict__ out) {
    extern __shared__ __align__(16) float sm[];
    int y = blockIdx.y, col0 = blockIdx.x << 7;
    int b = y >> 3, r0 = (y & 7) << 7;
    const float* A = g_attn + (size_t)(y << 7) * 1024;
    const float* res = g_cln + ((size_t)(b * Kc + Mc) + r0) * 1024 + col0;
    float* Cb = out + (size_t)(y << 7) * 1024 + col0;
    gemm_body<true>(A, Wo + col0, Cb, res, sm);
}

// ---------------------------------------------------------------------------
// Tensor-core flash attention with relative position skew.
// 128 threads (4 warps); warp w owns query rows [w*16, w*16+16).
// ---------------------------------------------------------------------------
#define OFF_V  (64 * 68)
#define OFF_PB (OFF_V + 64 * 72)
#define OFF_QP (OFF_PB + 128 * 68)
#define SM_FLOATS (OFF_QP + 64 * 132)

__global__ __launch_bounds__(128) void attn_tc(const float* __restrict__ pos_emb) {
    extern __shared__ __align__(16) float sm[];
    float* Ks = sm;                // [64][68]
    float* Vs = sm + OFF_V;        // [64][72]
    float* Pb = sm + OFF_PB;       // [128][68]  pos band (also Q staging)
    float* Qp = sm + OFF_QP;       // [64][132]  qpos band, reused for P

    int t = threadIdx.x, lane = t & 31, w = t >> 5;
    int g = lane >> 3, rr = lane & 7, R = lane >> 2, c2 = (lane & 3) << 1;
    int qi = 15 - (int)blockIdx.x;
    int s0 = qi << 6;
    int bh = blockIdx.y, b = bh >> 4, h = bh & 15;

    const float* qbase = g_q + ((size_t)(b * Sc + s0)) * HDc + h * 64;
    for (int e = t; e < 1024; e += 128) {
        int r = e >> 4, c4 = e & 15;
        *(float4*)&Pb[r * 68 + (c4 << 2)] =
            *(const float4*)(qbase + (size_t)r * HDc + (c4 << 2));
    }
    __syncthreads();
    uint32_t qf[8][4];
#pragma unroll
    for (int k8 = 0; k8 < 8; k8++)
        ldm4(qf[k8], sptr(&Pb[(w * 16 + rr + ((g & 1) << 3)) * 68 +
                              (k8 << 3) + ((g >> 1) << 2)]));

    float O[8][4];
#pragma unroll
    for (int nt = 0; nt < 8; nt++)
#pragma unroll
        for (int i = 0; i < 4; i++) O[nt][i] = 0.f;
    float m0 = -1e30f, m1 = -1e30f, l0 = 0.f, l1 = 0.f;

    const float* kbase = g_k + ((size_t)b * Kc) * HDc + h * 64;
    const float* vbase = g_v + ((size_t)b * Kc) * HDc + h * 64;
    const float* pbase = pos_emb + (size_t)b * Rc * DHc;
    int dq0 = w * 16 + R, dq1 = dq0 + 8;
    int ntiles = qi + 17;

    for (int kt = 0; kt < ntiles; kt++) {
        int k0 = kt << 6;
        int rr0 = k0 - s0 + (Sc - 64);
        __syncthreads();
        for (int e = t; e < 1024; e += 128) {
            int r = e >> 4, c4 = e & 15;
            cpa(sptr(&Ks[r * 68 + (c4 << 2)]),
                kbase + (size_t)(k0 + r) * HDc + (c4 << 2));
            cpa(sptr(&Vs[r * 72 + (c4 << 2)]),
                vbase + (size_t)(k0 + r) * HDc + (c4 << 2));
        }
        for (int e = t; e < 2048; e += 128) {
            int r = e >> 4, c4 = e & 15;
            cpa(sptr(&Pb[r * 68 + (c4 << 2)]),
                pbase + (size_t)(rr0 + r) * DHc + (c4 << 2));
        }
        CP_COMMIT;
        CP_WAIT(0);
        __syncthreads();

        // ---- qpos = Q @ pos_band^T  (64x128)
#pragma unroll
        for (int np = 0; np < 8; np++) {
            float qa[2][4] = {{0.f,0.f,0.f,0.f},{0.f,0.f,0.f,0.f}};
#pragma unroll
            for (int k8 = 0; k8 < 8; k8++) {
                uint32_t bb[4];
                ldm4(bb, sptr(&Pb[(np * 16 + rr + ((g >> 1) << 3)) * 68 +
                                  (k8 << 3) + ((g & 1) << 2)]));
                mma8(qa[0], qf[k8], bb[0], bb[1]);
                mma8(qa[1], qf[k8], bb[2], bb[3]);
            }
            float* q0 = &Qp[dq0 * 132 + np * 16];
            float* q1 = &Qp[dq1 * 132 + np * 16];
            q0[c2]     = qa[0][0]; q0[c2 + 1]     = qa[0][1];
            q1[c2]     = qa[0][2]; q1[c2 + 1]     = qa[0][3];
            q0[8 + c2] = qa[1][0]; q0[8 + c2 + 1] = qa[1][1];
            q1[8 + c2] = qa[1][2]; q1[8 + c2 + 1] = qa[1][3];
        }
        __syncwarp();

        // ---- scores = Q @ K^T (64x64)
        float sc[8][4];
#pragma unroll
        for (int nt = 0; nt < 8; nt++)
#pragma unroll
            for (int i = 0; i < 4; i++) sc[nt][i] = 0.f;
#pragma unroll
        for (int np = 0; np < 4; np++) {
#pragma unroll
            for (int k8 = 0; k8 < 8; k8++) {
                uint32_t bb[4];
                ldm4(bb, sptr(&Ks[(np * 16 + rr + ((g >> 1) << 3)) * 68 +
                                  (k8 << 3) + ((g & 1) << 2)]));
                mma8(sc[np * 2],     qf[k8], bb[0], bb[1]);
                mma8(sc[np * 2 + 1], qf[k8], bb[2], bb[3]);
            }
        }

        // ---- skew add + mask
#pragma unroll
        for (int nt = 0; nt < 8; nt++) {
#pragma unroll
            for (int j = 0; j < 2; j++) {
                int dk = (nt << 3) + c2 + j;
                float p0 = Qp[dq0 * 132 + dk - dq0 + 63];
                float p1 = Qp[dq1 * 132 + dk - dq1 + 63];
                bool mk0 = (k0 + dk) > (s0 + dq0 + Mc);
                bool mk1 = (k0 + dk) > (s0 + dq1 + Mc);
                sc[nt][j]     = mk0 ? -1e30f : (sc[nt][j] + p0) * 0.03125f;
                sc[nt][2 + j] = mk1 ? -1e30f : (sc[nt][2 + j] + p1) * 0.03125f;
            }
        }

        // ---- online softmax (quad-local rows)
        float mx0 = -1e30f, mx1 = -1e30f;
#pragma unroll
        for (int nt = 0; nt < 8; nt++) {
            mx0 = fmaxf(mx0, fmaxf(sc[nt][0], sc[nt][1]));
            mx1 = fmaxf(mx1, fmaxf(sc[nt][2], sc[nt][3]));
        }
        mx0 = fmaxf(mx0, __shfl_xor_sync(0xffffffffu, mx0, 1));
        mx0 = fmaxf(mx0, __shfl_xor_sync(0xffffffffu, mx0, 2));
        mx1 = fmaxf(mx1, __shfl_xor_sync(0xffffffffu, mx1, 1));
        mx1 = fmaxf(mx1, __shfl_xor_sync(0xffffffffu, mx1, 2));
        float mn0 = fmaxf(m0, mx0), mn1 = fmaxf(m1, mx1);
        float al0 = __expf(m0 - mn0), al1 = __expf(m1 - mn1);
        m0 = mn0; m1 = mn1;
        float su0 = 0.f, su1 = 0.f;
        __syncwarp();
#pragma unroll
        for (int nt = 0; nt < 8; nt++) {
            float p0 = __expf(sc[nt][0] - mn0), p1 = __expf(sc[nt][1] - mn0);
            float p2 = __expf(sc[nt][2] - mn1), p3 = __expf(sc[nt][3] - mn1);
            su0 += p0 + p1; su1 += p2 + p3;
            int dk = (nt << 3) + c2;
            Qp[dq0 * 132 + dk] = p0; Qp[dq0 * 132 + dk + 1] = p1;
            Qp[dq1 * 132 + dk] = p2; Qp[dq1 * 132 + dk + 1] = p3;
        }
        su0 += __shfl_xor_sync(0xffffffffu, su0, 1);
        su0 += __shfl_xor_sync(0xffffffffu, su0, 2);
        su1 += __shfl_xor_sync(0xffffffffu, su1, 1);
        su1 += __shfl_xor_sync(0xffffffffu, su1, 2);
        l0 = l0 * al0 + su0; l1 = l1 * al1 + su1;
#pragma unroll
        for (int nt = 0; nt < 8; nt++) {
            O[nt][0] *= al0; O[nt][1] *= al0;
            O[nt][2] *= al1; O[nt][3] *= al1;
        }
        __syncwarp();

        // ---- O += P @ V
#pragma unroll
        for (int k8 = 0; k8 < 8; k8++) {
            uint32_t pa[4];
            ldm4(pa, sptr(&Qp[(w * 16 + rr + ((g & 1) << 3)) * 132 +
                              (k8 << 3) + ((g >> 1) << 2)]));
#pragma unroll
            for (int nt = 0; nt < 8; nt++) {
                int n = (nt << 3) + (lane >> 2);
                uint32_t b0 = __float_as_uint(Vs[((k8 << 3) + (lane & 3)) * 72 + n]);
                uint32_t b1 = __float_as_uint(Vs[((k8 << 3) + 4 + (lane & 3)) * 72 + n]);
                mma8(O[nt], pa, b0, b1);
            }
        }
    }

    float i0 = 1.f / l0, i1 = 1.f / l1;
    float* obase = g_attn + ((size_t)(b * Sc + s0)) * HDc + h * 64;
#pragma unroll
    for (int nt = 0; nt < 8; nt++) {
        int c = (nt << 3) + c2;
        obase[(size_t)dq0 * HDc + c]     = O[nt][0] * i0;
        obase[(size_t)dq0 * HDc + c + 1] = O[nt][1] * i0;
        obase[(size_t)dq1 * HDc + c]     = O[nt][2] * i1;
        obase[(size_t)dq1 * HDc + c + 1] = O[nt][3] * i1;
    }
}

// ---------------------------------------------------------------------------
extern "C" void kernel_launch(void* const* d_in, const int* in_sizes, int n_in,
                              void* d_out, int out_size) {
    const float* hidden  = (const float*)d_in[0];
    const float* pos_emb = (const float*)d_in[1];
    const float* memory  = (const float*)d_in[2];
    // d_in[3] = mask (bool) — recomputed analytically
    const float* Wq = (const float*)d_in[4];
    const float* Wk = (const float*)d_in[5];
    const float* Wv = (const float*)d_in[6];
    const float* Wo = (const float*)d_in[7];
    const float* gamma = (const float*)d_in[8];
    const float* beta  = (const float*)d_in[9];
    float* out = (float*)d_out;

    ln_kernel<<<Bc * Kc, 256>>>(hidden, memory, gamma, beta);

    cudaFuncSetAttribute(proj_tc, cudaFuncAttributeMaxDynamicSharedMemorySize,
                         GEMM_SMEM_BYTES);
    cudaFuncSetAttribute(out_tc, cudaFuncAttributeMaxDynamicSharedMemorySize,
                         GEMM_SMEM_BYTES);
    proj_tc<<<dim3(8, 32, 3), 256, GEMM_SMEM_BYTES>>>(Wq, Wk, Wv);

    int attn_smem = SM_FLOATS * (int)sizeof(float);
    cudaFuncSetAttribute(attn_tc, cudaFuncAttributeMaxDynamicSharedMemorySize,
                         attn_smem);
    attn_tc<<<dim3(Sc / 64, Bc * Hc), 128, attn_smem>>>(pos_emb);

    out_tc<<<dim3(8, 16), 256, GEMM_SMEM_BYTES>>>(Wo, out);
}

// round 5
// speedup vs baseline: 7.0835x; 1.1011x over previous
#include <cuda_runtime.h>
#include <stdint.h>
#include <math.h>

#define Bc 2
#define Sc 1024
#define Mc 1024
#define Dc 1024
#define Hc 16
#define DHc 64
#define Kc 2048
#define Rc 4095
#define HDc 1024

// -------- scratch (static device globals; allocation is forbidden) --------
__device__ float g_cln[Bc * Kc * Dc];
__device__ float g_q[Bc * Sc * HDc];
__device__ float g_k[Bc * Kc * HDc];
__device__ float g_v[Bc * Kc * HDc];
__device__ float g_attn[Bc * Sc * HDc];

// ---------------------------------------------------------------------------
__device__ __forceinline__ uint32_t sptr(const void* p) {
    return (uint32_t)__cvta_generic_to_shared(p);
}
__device__ __forceinline__ void ldm4(uint32_t* r, uint32_t a) {
    asm volatile("ldmatrix.sync.aligned.m8n8.x4.shared.b16 {%0,%1,%2,%3},[%4];"
                 : "=r"(r[0]), "=r"(r[1]), "=r"(r[2]), "=r"(r[3]) : "r"(a));
}
__device__ __forceinline__ void mma8(float* d, const uint32_t* a,
                                     uint32_t b0, uint32_t b1) {
    asm volatile(
        "mma.sync.aligned.m16n8k8.row.col.f32.tf32.tf32.f32 "
        "{%0,%1,%2,%3},{%4,%5,%6,%7},{%8,%9},{%0,%1,%2,%3};"
        : "+f"(d[0]), "+f"(d[1]), "+f"(d[2]), "+f"(d[3])
        : "r"(a[0]), "r"(a[1]), "r"(a[2]), "r"(a[3]), "r"(b0), "r"(b1));
}
__device__ __forceinline__ void cpa(uint32_t d, const void* s) {
    asm volatile("cp.async.cg.shared.global [%0], [%1], 16;" :: "r"(d), "l"(s));
}
#define CP_COMMIT asm volatile("cp.async.commit_group;")
#define CP_WAIT(n) asm volatile("cp.async.wait_group %0;" :: "n"(n))

// ---------------------------------------------------------------------------
__global__ void ln_kernel(const float* __restrict__ hidden,
                          const float* __restrict__ memory,
                          const float* __restrict__ gamma,
                          const float* __restrict__ beta) {
    int row = blockIdx.x;
    int b = row / Kc, r = row % Kc;
    const float* src = (r < Mc) ? (memory + ((size_t)b * Mc + r) * Dc)
                                : (hidden + ((size_t)b * Sc + (r - Mc)) * Dc);
    int t = threadIdx.x;
    float x[4];
    float s = 0.f, sq = 0.f;
#pragma unroll
    for (int i = 0; i < 4; i++) {
        x[i] = src[t + 256 * i];
        s += x[i];
        sq += x[i] * x[i];
    }
#pragma unroll
    for (int m = 16; m; m >>= 1) {
        s  += __shfl_xor_sync(0xffffffffu, s, m);
        sq += __shfl_xor_sync(0xffffffffu, sq, m);
    }
    __shared__ float ss[8], ssq[8];
    int w = t >> 5, l = t & 31;
    if (l == 0) { ss[w] = s; ssq[w] = sq; }
    __syncthreads();
    if (w == 0) {
        float sv  = (l < 8) ? ss[l]  : 0.f;
        float sqv = (l < 8) ? ssq[l] : 0.f;
#pragma unroll
        for (int m = 4; m; m >>= 1) {
            sv  += __shfl_xor_sync(0xffffffffu, sv, m);
            sqv += __shfl_xor_sync(0xffffffffu, sqv, m);
        }
        if (l == 0) { ss[0] = sv; ssq[0] = sqv; }
    }
    __syncthreads();
    float mean = ss[0] * (1.f / Dc);
    float var  = ssq[0] * (1.f / Dc) - mean * mean;
    float inv  = rsqrtf(var + 1e-5f);
    float* dst = g_cln + (size_t)row * Dc;
#pragma unroll
    for (int i = 0; i < 4; i++) {
        int d = t + 256 * i;
        dst[d] = (x[i] - mean) * inv * gamma[d] + beta[d];
    }
}

// ---------------------------------------------------------------------------
// Pipelined tf32 GEMM body: C128x128 = A[128x1024] @ W[1024x128] (+residual)
// 8 warps (4m x 2n), 3-stage cp.async pipeline, BK=32.
// ---------------------------------------------------------------------------
#define ASZ (128 * 36)
#define BSZ (32 * 136)
#define STGF (ASZ + BSZ)
#define GEMM_SMEM_BYTES (3 * STGF * 4)

template <bool RES>
__device__ __forceinline__ void gemm_body(const float* __restrict__ A,
                                          const float* __restrict__ W,
                                          float* __restrict__ C,
                                          const float* __restrict__ res,
                                          float* sm) {
    int t = threadIdx.x, lane = t & 31, w = t >> 5;
    int wm = (w >> 1) << 5, wn = (w & 1) << 6;
    int g = lane >> 3, rr = lane & 7;

    auto load_stage = [&](int ki) {
        float* As = sm + (ki % 3) * STGF;
        float* Bs = As + ASZ;
        int k0 = ki << 5;
#pragma unroll
        for (int it = 0; it < 4; it++) {
            int c = t + (it << 8);
            int r = c >> 3, qd = c & 7;
            cpa(sptr(As + r * 36 + (qd << 2)),
                A + (size_t)r * 1024 + k0 + (qd << 2));
        }
#pragma unroll
        for (int it = 0; it < 4; it++) {
            int c = t + (it << 8);
            int r = c >> 5, qd = c & 31;
            cpa(sptr(Bs + r * 136 + (qd << 2)),
                W + (size_t)(k0 + r) * 1024 + (qd << 2));
        }
    };

#pragma unroll
    for (int s = 0; s < 3; s++) { load_stage(s); CP_COMMIT; }

    float acc[2][8][4];
#pragma unroll
    for (int mt = 0; mt < 2; mt++)
#pragma unroll
        for (int nt = 0; nt < 8; nt++)
#pragma unroll
            for (int i = 0; i < 4; i++) acc[mt][nt][i] = 0.f;

    for (int i = 0; i < 32; i++) {
        CP_WAIT(2);
        __syncthreads();
        float* As = sm + (i % 3) * STGF;
        float* Bs = As + ASZ;
#pragma unroll
        for (int kk = 0; kk < 32; kk += 8) {
            uint32_t a0[4], a1[4];
            ldm4(a0, sptr(&As[(wm + rr + ((g & 1) << 3)) * 36 +
                              kk + ((g >> 1) << 2)]));
            ldm4(a1, sptr(&As[(wm + 16 + rr + ((g & 1) << 3)) * 36 +
                              kk + ((g >> 1) << 2)]));
#pragma unroll
            for (int nt = 0; nt < 8; nt++) {
                int n = wn + (nt << 3) + (lane >> 2);
                uint32_t b0 = __float_as_uint(Bs[(kk + (lane & 3)) * 136 + n]);
                uint32_t b1 = __float_as_uint(Bs[(kk + 4 + (lane & 3)) * 136 + n]);
                mma8(acc[0][nt], a0, b0, b1);
                mma8(acc[1][nt], a1, b0, b1);
            }
        }
        __syncthreads();
        if (i + 3 < 32) load_stage(i + 3);
        CP_COMMIT;
    }

    int rA = wm + (lane >> 2);
#pragma unroll
    for (int mt = 0; mt < 2; mt++) {
        int r0 = rA + mt * 16, r1 = r0 + 8;
#pragma unroll
        for (int nt = 0; nt < 8; nt++) {
            int c = wn + (nt << 3) + ((lane & 3) << 1);
            float v0 = acc[mt][nt][0], v1 = acc[mt][nt][1];
            float v2 = acc[mt][nt][2], v3 = acc[mt][nt][3];
            if (RES) {
                const float* rs0 = res + (size_t)r0 * 1024 + c;
                const float* rs1 = res + (size_t)r1 * 1024 + c;
                v0 += rs0[0]; v1 += rs0[1];
                v2 += rs1[0]; v3 += rs1[1];
            }
            C[(size_t)r0 * 1024 + c] = v0; C[(size_t)r0 * 1024 + c + 1] = v1;
            C[(size_t)r1 * 1024 + c] = v2; C[(size_t)r1 * 1024 + c + 1] = v3;
        }
    }
}

// Fused Q/K/V projection: grid (8, 32, 3); z: 0=K, 1=V, 2=Q (y<16)
__global__ __launch_bounds__(256, 2) void proj_tc(const float* __restrict__ Wq,
                                                  const float* __restrict__ Wk,
                                                  const float* __restrict__ Wv) {
    extern __shared__ __align__(16) float sm[];
    int task = blockIdx.z, y = blockIdx.y, col0 = blockIdx.x << 7;
    const float* A;
    const float* W;
    float* Cb;
    if (task == 0) {
        A = g_cln + (size_t)(y << 7) * 1024; W = Wk;
        Cb = g_k + (size_t)(y << 7) * 1024 + col0;
    } else if (task == 1) {
        A = g_cln + (size_t)(y << 7) * 1024; W = Wv;
        Cb = g_v + (size_t)(y << 7) * 1024 + col0;
    } else {
        if (y >= 16) return;
        int b = y >> 3, r0 = (y & 7) << 7;
        A = g_cln + ((size_t)(b * Kc + Mc) + r0) * 1024; W = Wq;
        Cb = g_q + ((size_t)(b * Sc) + r0) * 1024 + col0;
    }
    gemm_body<false>(A, W + col0, Cb, nullptr, sm);
}

// Output projection + residual: grid (8, 16)
__global__ __launch_bounds__(256, 2) void out_tc(const float* __restrict__ Wo,
                                                 float* __restrict__ out) {
    extern __shared__ __align__(16) float sm[];
    int y = blockIdx.y, col0 = blockIdx.x << 7;
    int b = y >> 3, r0 = (y & 7) << 7;
    const float* A = g_attn + (size_t)(y << 7) * 1024;
    const float* res = g_cln + ((size_t)(b * Kc + Mc) + r0) * 1024 + col0;
    float* Cb = out + (size_t)(y << 7) * 1024 + col0;
    gemm_body<true>(A, Wo + col0, Cb, res, sm);
}

// ---------------------------------------------------------------------------
// Tensor-core flash attention, rolling cp.async pipeline.
// 128 threads (4 warps); warp w owns query rows [w*16, w*16+16).
// smem: Ks[64][68] | Vs[64][72] | pos pages P0,P1 [64][68] | Qp[64][132]
// ---------------------------------------------------------------------------
#define OFF_V  (64 * 68)
#define OFF_P0 (OFF_V + 64 * 72)
#define OFF_P1 (OFF_P0 + 64 * 68)
#define OFF_QP (OFF_P1 + 64 * 68)
#define SM_FLOATS (OFF_QP + 64 * 132)

__global__ __launch_bounds__(128) void attn_tc(const float* __restrict__ pos_emb) {
    extern __shared__ __align__(16) float sm[];
    float* Ks = sm;
    float* Vs = sm + OFF_V;
    float* P0 = sm + OFF_P0;
    float* P1 = sm + OFF_P1;
    float* Qp = sm + OFF_QP;

    int t = threadIdx.x, lane = t & 31, w = t >> 5;
    int g = lane >> 3, rr = lane & 7, R = lane >> 2, c2 = (lane & 3) << 1;
    int qi = 15 - (int)blockIdx.x;
    int s0 = qi << 6;
    int bh = blockIdx.y, b = bh >> 4, h = bh & 15;

    const float* qbase = g_q + ((size_t)(b * Sc + s0)) * HDc + h * 64;
    const float* kbase = g_k + ((size_t)b * Kc) * HDc + h * 64;
    const float* vbase = g_v + ((size_t)b * Kc) * HDc + h * 64;
    const float* pbase = pos_emb + (size_t)b * Rc * DHc;
    int rr0base = 960 - s0;   // pos row base for kt=0 band
    int ntiles = qi + 17;

    // ---- prologue: 4 cp.async groups: Q | pos pages 0+1 | K(0) | V(0)
    for (int e = t; e < 1024; e += 128) {
        int r = e >> 4, c = e & 15;
        cpa(sptr(&Qp[r * 132 + (c << 2)]), qbase + (size_t)r * HDc + (c << 2));
    }
    CP_COMMIT;
    for (int e = t; e < 1024; e += 128) {
        int r = e >> 4, c = e & 15;
        cpa(sptr(&P0[r * 68 + (c << 2)]),
            pbase + (size_t)(rr0base + r) * DHc + (c << 2));
        cpa(sptr(&P1[r * 68 + (c << 2)]),
            pbase + (size_t)(rr0base + 64 + r) * DHc + (c << 2));
    }
    CP_COMMIT;
    for (int e = t; e < 1024; e += 128) {
        int r = e >> 4, c = e & 15;
        cpa(sptr(&Ks[r * 68 + (c << 2)]), kbase + (size_t)r * HDc + (c << 2));
    }
    CP_COMMIT;
    for (int e = t; e < 1024; e += 128) {
        int r = e >> 4, c = e & 15;
        cpa(sptr(&Vs[r * 72 + (c << 2)]), vbase + (size_t)r * HDc + (c << 2));
    }
    CP_COMMIT;

    CP_WAIT(3);
    __syncthreads();
    uint32_t qf[8][4];
#pragma unroll
    for (int k8 = 0; k8 < 8; k8++)
        ldm4(qf[k8], sptr(&Qp[(w * 16 + rr + ((g & 1) << 3)) * 132 +
                              (k8 << 3) + ((g >> 1) << 2)]));

    float O[8][4];
#pragma unroll
    for (int nt = 0; nt < 8; nt++)
#pragma unroll
        for (int i = 0; i < 4; i++) O[nt][i] = 0.f;
    float m0 = -1e30f, m1 = -1e30f, l0 = 0.f, l1 = 0.f;
    int dq0 = w * 16 + R, dq1 = dq0 + 8;

    for (int kt = 0; kt < ntiles; kt++) {
        int k0 = kt << 6;
        float* PL = (kt & 1) ? P1 : P0;   // band cols 0-63
        float* PH = (kt & 1) ? P0 : P1;   // band cols 64-127

        CP_WAIT(2);          // pos pages for this tile ready
        __syncthreads();

        // ---- qpos = Q @ pos_band^T  (64x128)
#pragma unroll
        for (int np = 0; np < 8; np++) {
            const float* base = (np < 4) ? PL : PH;
            int rl = ((np & 3) << 4) + rr + ((g >> 1) << 3);
            float qa[2][4] = {{0.f,0.f,0.f,0.f},{0.f,0.f,0.f,0.f}};
#pragma unroll
            for (int k8 = 0; k8 < 8; k8++) {
                uint32_t bb[4];
                ldm4(bb, sptr(&base[rl * 68 + (k8 << 3) + ((g & 1) << 2)]));
                mma8(qa[0], qf[k8], bb[0], bb[1]);
                mma8(qa[1], qf[k8], bb[2], bb[3]);
            }
            float* q0 = &Qp[dq0 * 132 + (np << 4)];
            float* q1 = &Qp[dq1 * 132 + (np << 4)];
            *(float2*)(q0 + c2)     = make_float2(qa[0][0], qa[0][1]);
            *(float2*)(q1 + c2)     = make_float2(qa[0][2], qa[0][3]);
            *(float2*)(q0 + 8 + c2) = make_float2(qa[1][0], qa[1][1]);
            *(float2*)(q1 + 8 + c2) = make_float2(qa[1][2], qa[1][3]);
        }
        __syncthreads();     // all warps done reading PL

        // prefetch next pos page (rows rr0+128..191) into PL
        {
            int gr = rr0base + k0 + 128;
            for (int e = t; e < 1024; e += 128) {
                int r = e >> 4, c = e & 15;
                cpa(sptr(&PL[r * 68 + (c << 2)]),
                    pbase + (size_t)(gr + r) * DHc + (c << 2));
            }
        }
        CP_COMMIT;

        CP_WAIT(2);          // K tile ready
        __syncthreads();

        // ---- scores = Q @ K^T (64x64)
        float sc[8][4];
#pragma unroll
        for (int nt = 0; nt < 8; nt++)
#pragma unroll
            for (int i = 0; i < 4; i++) sc[nt][i] = 0.f;
#pragma unroll
        for (int np = 0; np < 4; np++) {
#pragma unroll
            for (int k8 = 0; k8 < 8; k8++) {
                uint32_t bb[4];
                ldm4(bb, sptr(&Ks[((np << 4) + rr + ((g >> 1) << 3)) * 68 +
                                  (k8 << 3) + ((g & 1) << 2)]));
                mma8(sc[np * 2],     qf[k8], bb[0], bb[1]);
                mma8(sc[np * 2 + 1], qf[k8], bb[2], bb[3]);
            }
        }
        __syncthreads();     // all warps done reading Ks

        // prefetch K(kt+1) (clamped)
        {
            int kb = k0 + 64;
            for (int e = t; e < 1024; e += 128) {
                int r = e >> 4, c = e & 15;
                int krow = kb + r; if (krow > Kc - 1) krow = Kc - 1;
                cpa(sptr(&Ks[r * 68 + (c << 2)]),
                    kbase + (size_t)krow * HDc + (c << 2));
            }
        }
        CP_COMMIT;

        // ---- skew add + mask
#pragma unroll
        for (int nt = 0; nt < 8; nt++) {
#pragma unroll
            for (int j = 0; j < 2; j++) {
                int dk = (nt << 3) + c2 + j;
                float p0 = Qp[dq0 * 132 + dk - dq0 + 63];
                float p1 = Qp[dq1 * 132 + dk - dq1 + 63];
                bool mk0 = (k0 + dk) > (s0 + dq0 + Mc);
                bool mk1 = (k0 + dk) > (s0 + dq1 + Mc);
                sc[nt][j]     = mk0 ? -1e30f : (sc[nt][j] + p0) * 0.03125f;
                sc[nt][2 + j] = mk1 ? -1e30f : (sc[nt][2 + j] + p1) * 0.03125f;
            }
        }

        // ---- online softmax (quad-local rows)
        float mx0 = -1e30f, mx1 = -1e30f;
#pragma unroll
        for (int nt = 0; nt < 8; nt++) {
            mx0 = fmaxf(mx0, fmaxf(sc[nt][0], sc[nt][1]));
            mx1 = fmaxf(mx1, fmaxf(sc[nt][2], sc[nt][3]));
        }
        mx0 = fmaxf(mx0, __shfl_xor_sync(0xffffffffu, mx0, 1));
        mx0 = fmaxf(mx0, __shfl_xor_sync(0xffffffffu, mx0, 2));
        mx1 = fmaxf(mx1, __shfl_xor_sync(0xffffffffu, mx1, 1));
        mx1 = fmaxf(mx1, __shfl_xor_sync(0xffffffffu, mx1, 2));
        float mn0 = fmaxf(m0, mx0), mn1 = fmaxf(m1, mx1);
        float al0 = __expf(m0 - mn0), al1 = __expf(m1 - mn1);
        m0 = mn0; m1 = mn1;
        float su0 = 0.f, su1 = 0.f;
#pragma unroll
        for (int nt = 0; nt < 8; nt++) {
            float p0 = __expf(sc[nt][0] - mn0), p1 = __expf(sc[nt][1] - mn0);
            float p2 = __expf(sc[nt][2] - mn1), p3 = __expf(sc[nt][3] - mn1);
            su0 += p0 + p1; su1 += p2 + p3;
            int dk = (nt << 3) + c2;
            *(float2*)(&Qp[dq0 * 132 + dk]) = make_float2(p0, p1);
            *(float2*)(&Qp[dq1 * 132 + dk]) = make_float2(p2, p3);
        }
        su0 += __shfl_xor_sync(0xffffffffu, su0, 1);
        su0 += __shfl_xor_sync(0xffffffffu, su0, 2);
        su1 += __shfl_xor_sync(0xffffffffu, su1, 1);
        su1 += __shfl_xor_sync(0xffffffffu, su1, 2);
        l0 = l0 * al0 + su0; l1 = l1 * al1 + su1;
#pragma unroll
        for (int nt = 0; nt < 8; nt++) {
            O[nt][0] *= al0; O[nt][1] *= al0;
            O[nt][2] *= al1; O[nt][3] *= al1;
        }
        __syncwarp();

        CP_WAIT(2);          // V tile ready
        __syncthreads();

        // ---- O += P @ V
#pragma unroll
        for (int k8 = 0; k8 < 8; k8++) {
            uint32_t pa[4];
            ldm4(pa, sptr(&Qp[(w * 16 + rr + ((g & 1) << 3)) * 132 +
                              (k8 << 3) + ((g >> 1) << 2)]));
#pragma unroll
            for (int nt = 0; nt < 8; nt++) {
                int n = (nt << 3) + (lane >> 2);
                uint32_t b0 = __float_as_uint(Vs[((k8 << 3) + (lane & 3)) * 72 + n]);
                uint32_t b1 = __float_as_uint(Vs[((k8 << 3) + 4 + (lane & 3)) * 72 + n]);
                mma8(O[nt], pa, b0, b1);
            }
        }
        __syncthreads();     // all warps done reading Vs

        // prefetch V(kt+1) (clamped)
        {
            int kb = k0 + 64;
            for (int e = t; e < 1024; e += 128) {
                int r = e >> 4, c = e & 15;
                int krow = kb + r; if (krow > Kc - 1) krow = Kc - 1;
                cpa(sptr(&Vs[r * 72 + (c << 2)]),
                    vbase + (size_t)krow * HDc + (c << 2));
            }
        }
        CP_COMMIT;
    }
    CP_WAIT(0);

    float i0 = 1.f / l0, i1 = 1.f / l1;
    float* obase = g_attn + ((size_t)(b * Sc + s0)) * HDc + h * 64;
#pragma unroll
    for (int nt = 0; nt < 8; nt++) {
        int c = (nt << 3) + c2;
        *(float2*)(&obase[(size_t)dq0 * HDc + c]) =
            make_float2(O[nt][0] * i0, O[nt][1] * i0);
        *(float2*)(&obase[(size_t)dq1 * HDc + c]) =
            make_float2(O[nt][2] * i1, O[nt][3] * i1);
    }
}

// ---------------------------------------------------------------------------
extern "C" void kernel_launch(void* const* d_in, const int* in_sizes, int n_in,
                              void* d_out, int out_size) {
    const float* hidden  = (const float*)d_in[0];
    const float* pos_emb = (const float*)d_in[1];
    const float* memory  = (const float*)d_in[2];
    // d_in[3] = mask (bool) — recomputed analytically
    const float* Wq = (const float*)d_in[4];
    const float* Wk = (const float*)d_in[5];
    const float* Wv = (const float*)d_in[6];
    const float* Wo = (const float*)d_in[7];
    const float* gamma = (const float*)d_in[8];
    const float* beta  = (const float*)d_in[9];
    float* out = (float*)d_out;

    ln_kernel<<<Bc * Kc, 256>>>(hidden, memory, gamma, beta);

    cudaFuncSetAttribute(proj_tc, cudaFuncAttributeMaxDynamicSharedMemorySize,
                         GEMM_SMEM_BYTES);
    cudaFuncSetAttribute(out_tc, cudaFuncAttributeMaxDynamicSharedMemorySize,
                         GEMM_SMEM_BYTES);
    proj_tc<<<dim3(8, 32, 3), 256, GEMM_SMEM_BYTES>>>(Wq, Wk, Wv);

    int attn_smem = SM_FLOATS * (int)sizeof(float);
    cudaFuncSetAttribute(attn_tc, cudaFuncAttributeMaxDynamicSharedMemorySize,
                         attn_smem);
    attn_tc<<<dim3(Sc / 64, Bc * Hc), 128, attn_smem>>>(pos_emb);

    out_tc<<<dim3(8, 16), 256, GEMM_SMEM_BYTES>>>(Wo, out);
}

// round 6
// speedup vs baseline: 10.3931x; 1.4672x over previous
#include <cuda_runtime.h>
#include <cuda_fp16.h>
#include <stdint.h>

#define Bc 2
#define Sc 1024
#define Mc 1024
#define Hc 16
#define Kc 2048
#define Rc 4095

// -------- scratch (static device globals; allocation is forbidden) --------
__device__ __half g_clnh[4096 * 1024];   // LN(concat) as fp16 (GEMM A operand)
__device__ float  g_hln [2048 * 1024];   // exact fp32 h_ln (residual)
__device__ __half g_qh  [2048 * 1024];
__device__ __half g_kh  [4096 * 1024];
__device__ __half g_vh  [4096 * 1024];
__device__ __half g_attnh[2048 * 1024];
__device__ __half g_wth [4 * 1024 * 1024]; // Wq,Wk,Wv,Wo transposed [n][k] fp16
__device__ __half g_posh[Bc * Rc * 64];

// ---------------------------------------------------------------------------
__device__ __forceinline__ uint32_t sptr(const void* p) {
    return (uint32_t)__cvta_generic_to_shared(p);
}
__device__ __forceinline__ void ldm4(uint32_t* r, uint32_t a) {
    asm volatile("ldmatrix.sync.aligned.m8n8.x4.shared.b16 {%0,%1,%2,%3},[%4];"
                 : "=r"(r[0]), "=r"(r[1]), "=r"(r[2]), "=r"(r[3]) : "r"(a));
}
__device__ __forceinline__ void ldm4t(uint32_t* r, uint32_t a) {
    asm volatile("ldmatrix.sync.aligned.m8n8.x4.trans.shared.b16 {%0,%1,%2,%3},[%4];"
                 : "=r"(r[0]), "=r"(r[1]), "=r"(r[2]), "=r"(r[3]) : "r"(a));
}
__device__ __forceinline__ void mma16(float* d, const uint32_t* a,
                                      uint32_t b0, uint32_t b1) {
    asm volatile(
        "mma.sync.aligned.m16n8k16.row.col.f32.f16.f16.f32 "
        "{%0,%1,%2,%3},{%4,%5,%6,%7},{%8,%9},{%0,%1,%2,%3};"
        : "+f"(d[0]), "+f"(d[1]), "+f"(d[2]), "+f"(d[3])
        : "r"(a[0]), "r"(a[1]), "r"(a[2]), "r"(a[3]), "r"(b0), "r"(b1));
}
__device__ __forceinline__ void cpa(uint32_t d, const void* s) {
    asm volatile("cp.async.cg.shared.global [%0], [%1], 16;" :: "r"(d), "l"(s));
}
#define CP_COMMIT asm volatile("cp.async.commit_group;")
#define CP_WAIT(n) asm volatile("cp.async.wait_group %0;" :: "n"(n))

// ---------------------------------------------------------------------------
// Weight transpose + fp16 convert: Wt[n][k] = W[k][n]
// ---------------------------------------------------------------------------
__global__ void wtrans_kernel(const float* __restrict__ Wq,
                              const float* __restrict__ Wk,
                              const float* __restrict__ Wv,
                              const float* __restrict__ Wo) {
    __shared__ float tile[32][33];
    int z = blockIdx.z;
    const float* W = (z == 0) ? Wq : (z == 1) ? Wk : (z == 2) ? Wv : Wo;
    __half* Wt = g_wth + (size_t)z * 1024 * 1024;
    int bx = blockIdx.x << 5, by = blockIdx.y << 5;  // bx: n, by: k
    int tx = threadIdx.x, ty = threadIdx.y;
#pragma unroll
    for (int i = 0; i < 32; i += 8)
        tile[ty + i][tx] = W[(size_t)(by + ty + i) * 1024 + bx + tx];
    __syncthreads();
#pragma unroll
    for (int i = 0; i < 32; i += 8)
        Wt[(size_t)(bx + ty + i) * 1024 + by + tx] = __float2half(tile[tx][ty + i]);
}

__global__ void posconv_kernel(const float* __restrict__ p) {
    int i = blockIdx.x * 256 + threadIdx.x;
    if (i < Bc * Rc * 64) g_posh[i] = __float2half(p[i]);
}

// ---------------------------------------------------------------------------
__global__ void ln_kernel(const float* __restrict__ hidden,
                          const float* __restrict__ memory,
                          const float* __restrict__ gamma,
                          const float* __restrict__ beta) {
    int row = blockIdx.x;
    int b = row / Kc, r = row % Kc;
    const float* src = (r < Mc) ? (memory + ((size_t)b * Mc + r) * 1024)
                                : (hidden + ((size_t)b * Sc + (r - Mc)) * 1024);
    int t = threadIdx.x;
    float x[4];
    float s = 0.f, sq = 0.f;
#pragma unroll
    for (int i = 0; i < 4; i++) {
        x[i] = src[t + 256 * i];
        s += x[i];
        sq += x[i] * x[i];
    }
#pragma unroll
    for (int m = 16; m; m >>= 1) {
        s  += __shfl_xor_sync(0xffffffffu, s, m);
        sq += __shfl_xor_sync(0xffffffffu, sq, m);
    }
    __shared__ float ss[8], ssq[8];
    int w = t >> 5, l = t & 31;
    if (l == 0) { ss[w] = s; ssq[w] = sq; }
    __syncthreads();
    if (w == 0) {
        float sv  = (l < 8) ? ss[l]  : 0.f;
        float sqv = (l < 8) ? ssq[l] : 0.f;
#pragma unroll
        for (int m = 4; m; m >>= 1) {
            sv  += __shfl_xor_sync(0xffffffffu, sv, m);
            sqv += __shfl_xor_sync(0xffffffffu, sqv, m);
        }
        if (l == 0) { ss[0] = sv; ssq[0] = sqv; }
    }
    __syncthreads();
    float mean = ss[0] * (1.f / 1024.f);
    float var  = ssq[0] * (1.f / 1024.f) - mean * mean;
    float inv  = rsqrtf(var + 1e-5f);
    __half* dsth = g_clnh + (size_t)row * 1024;
    float*  dstf = (r >= Mc) ? (g_hln + ((size_t)b * Sc + (r - Mc)) * 1024) : nullptr;
#pragma unroll
    for (int i = 0; i < 4; i++) {
        int d = t + 256 * i;
        float v = (x[i] - mean) * inv * gamma[d] + beta[d];
        dsth[d] = __float2half(v);
        if (dstf) dstf[d] = v;
    }
}

// ---------------------------------------------------------------------------
// fp16 tensor-core GEMM body: C[128x128] = A[128x1024] @ Wt[128x1024]^T
// A: [m][k] half; Wt: [n][k] half (pre-transposed). 3-stage cp.async, BK=32.
// MODE 0: store half; MODE 1: store fp32 + residual.
// ---------------------------------------------------------------------------
#define GASZ (128 * 40)
#define GSTG (2 * GASZ)
#define GEMM_SMEM_BYTES (3 * GSTG * 2)

template <int MODE>
__device__ __forceinline__ void gemm_body(const __half* __restrict__ A,
                                          const __half* __restrict__ Wt,
                                          __half* __restrict__ Ch,
                                          float* __restrict__ Cf,
                                          const float* __restrict__ res,
                                          __half* sm) {
    int t = threadIdx.x, lane = t & 31, w = t >> 5;
    int wm = (w >> 1) << 5, wn = (w & 1) << 6;

    auto load_stage = [&](int ki) {
        __half* As = sm + (ki % 3) * GSTG;
        __half* Bs = As + GASZ;
        int k0 = ki << 5;
#pragma unroll
        for (int it = 0; it < 2; it++) {
            int e = t + (it << 8);
            int r = e >> 2, c = e & 3;
            cpa(sptr(As + r * 40 + (c << 3)), A + (size_t)r * 1024 + k0 + (c << 3));
            cpa(sptr(Bs + r * 40 + (c << 3)), Wt + (size_t)r * 1024 + k0 + (c << 3));
        }
    };

#pragma unroll
    for (int s = 0; s < 3; s++) { load_stage(s); CP_COMMIT; }

    float acc[2][8][4];
#pragma unroll
    for (int mt = 0; mt < 2; mt++)
#pragma unroll
        for (int nt = 0; nt < 8; nt++)
#pragma unroll
            for (int i = 0; i < 4; i++) acc[mt][nt][i] = 0.f;

    for (int i = 0; i < 32; i++) {
        CP_WAIT(2);
        __syncthreads();
        __half* As = sm + (i % 3) * GSTG;
        __half* Bs = As + GASZ;
#pragma unroll
        for (int kc = 0; kc < 2; kc++) {
            uint32_t am[2][4];
#pragma unroll
            for (int mt = 0; mt < 2; mt++)
                ldm4(am[mt], sptr(As + (wm + mt * 16 + (lane & 15)) * 40 +
                                  (kc << 4) + ((lane >> 4) << 3)));
#pragma unroll
            for (int np = 0; np < 4; np++) {
                uint32_t bb[4];
                ldm4(bb, sptr(Bs + (wn + (np << 4) + (lane & 7) + ((lane >> 4) << 3)) * 40 +
                              (kc << 4) + (((lane >> 3) & 1) << 3)));
                mma16(acc[0][np * 2],     am[0], bb[0], bb[1]);
                mma16(acc[0][np * 2 + 1], am[0], bb[2], bb[3]);
                mma16(acc[1][np * 2],     am[1], bb[0], bb[1]);
                mma16(acc[1][np * 2 + 1], am[1], bb[2], bb[3]);
            }
        }
        __syncthreads();
        if (i + 3 < 32) load_stage(i + 3);
        CP_COMMIT;
    }

    int R = lane >> 2, c2 = (lane & 3) << 1;
#pragma unroll
    for (int mt = 0; mt < 2; mt++) {
        int r0 = wm + mt * 16 + R, r1 = r0 + 8;
#pragma unroll
        for (int nt = 0; nt < 8; nt++) {
            int c = wn + (nt << 3) + c2;
            if (MODE == 0) {
                *(__half2*)(Ch + (size_t)r0 * 1024 + c) =
                    __floats2half2_rn(acc[mt][nt][0], acc[mt][nt][1]);
                *(__half2*)(Ch + (size_t)r1 * 1024 + c) =
                    __floats2half2_rn(acc[mt][nt][2], acc[mt][nt][3]);
            } else {
                const float* rs0 = res + (size_t)r0 * 1024 + c;
                const float* rs1 = res + (size_t)r1 * 1024 + c;
                Cf[(size_t)r0 * 1024 + c]     = acc[mt][nt][0] + rs0[0];
                Cf[(size_t)r0 * 1024 + c + 1] = acc[mt][nt][1] + rs0[1];
                Cf[(size_t)r1 * 1024 + c]     = acc[mt][nt][2] + rs1[0];
                Cf[(size_t)r1 * 1024 + c + 1] = acc[mt][nt][3] + rs1[1];
            }
        }
    }
}

// Fused Q/K/V projection: grid (8, 32, 3); z: 0=K, 1=V, 2=Q (y<16)
__global__ __launch_bounds__(256, 2) void proj_tc() {
    extern __shared__ __align__(16) __half smh[];
    int task = blockIdx.z, y = blockIdx.y, col0 = blockIdx.x << 7;
    const __half* A;
    const __half* Wt;
    __half* Cb;
    if (task == 0) {
        A = g_clnh + (size_t)(y << 7) * 1024;
        Wt = g_wth + (1u << 20) + (size_t)col0 * 1024;
        Cb = g_kh + (size_t)(y << 7) * 1024 + col0;
    } else if (task == 1) {
        A = g_clnh + (size_t)(y << 7) * 1024;
        Wt = g_wth + (2u << 20) + (size_t)col0 * 1024;
        Cb = g_vh + (size_t)(y << 7) * 1024 + col0;
    } else {
        if (y >= 16) return;
        int b = y >> 3, r0 = (y & 7) << 7;
        A = g_clnh + ((size_t)(b * Kc + Mc) + r0) * 1024;
        Wt = g_wth + (size_t)col0 * 1024;
        Cb = g_qh + ((size_t)(b * Sc) + r0) * 1024 + col0;
    }
    gemm_body<0>(A, Wt, Cb, nullptr, nullptr, smh);
}

// Output projection + residual: grid (8, 16)
__global__ __launch_bounds__(256, 2) void out_tc(float* __restrict__ out) {
    extern __shared__ __align__(16) __half smh[];
    int y = blockIdx.y, col0 = blockIdx.x << 7;
    const __half* A = g_attnh + (size_t)(y << 7) * 1024;
    const __half* Wt = g_wth + (3u << 20) + (size_t)col0 * 1024;
    const float* res = g_hln + (size_t)(y << 7) * 1024 + col0;
    float* Cf = out + (size_t)(y << 7) * 1024 + col0;
    gemm_body<1>(A, Wt, nullptr, Cf, res, smh);
}

// ---------------------------------------------------------------------------
// fp16 tensor-core flash attention, rolling cp.async pipeline.
// 128 threads (4 warps); warp w owns query rows [w*16, w*16+16).
// ---------------------------------------------------------------------------
#define AB_PQ 0
#define AB_KS 9216
#define AB_VS 18432
#define AB_P0 27648
#define AB_P1 36864
#define AB_QP 46080
#define ATTN_SMEM_BYTES (AB_QP + 64 * 132 * 4)

__global__ __launch_bounds__(128) void attn_tc() {
    extern __shared__ __align__(16) char smb[];
    __half* Pq = (__half*)(smb + AB_PQ);   // Q staging, then probs P [64][72]
    __half* Ks = (__half*)(smb + AB_KS);   // [64][72]
    __half* Vs = (__half*)(smb + AB_VS);   // [64][72]
    __half* Pp0 = (__half*)(smb + AB_P0);  // pos page [64][72]
    __half* Pp1 = (__half*)(smb + AB_P1);
    float* Qp = (float*)(smb + AB_QP);     // qpos band fp32 [64][132]

    int t = threadIdx.x, lane = t & 31, w = t >> 5;
    int R = lane >> 2, c2 = (lane & 3) << 1;
    int qi = 15 - (int)blockIdx.x;
    int s0 = qi << 6;
    int bh = blockIdx.y, b = bh >> 4, h = bh & 15;

    const __half* qbase = g_qh + ((size_t)(b * Sc + s0)) * 1024 + h * 64;
    const __half* kbase = g_kh + ((size_t)b * Kc) * 1024 + h * 64;
    const __half* vbase = g_vh + ((size_t)b * Kc) * 1024 + h * 64;
    const __half* pbase = g_posh + (size_t)b * Rc * 64;
    int rr0base = 960 - s0;
    int ntiles = qi + 17;

    // prologue: Q | pos pages | K0 | V0
    for (int e = t; e < 512; e += 128) {
        int r = e >> 3, c = e & 7;
        cpa(sptr(Pq + r * 72 + (c << 3)), qbase + (size_t)r * 1024 + (c << 3));
    }
    CP_COMMIT;
    for (int e = t; e < 512; e += 128) {
        int r = e >> 3, c = e & 7;
        cpa(sptr(Pp0 + r * 72 + (c << 3)),
            pbase + (size_t)(rr0base + r) * 64 + (c << 3));
        cpa(sptr(Pp1 + r * 72 + (c << 3)),
            pbase + (size_t)(rr0base + 64 + r) * 64 + (c << 3));
    }
    CP_COMMIT;
    for (int e = t; e < 512; e += 128) {
        int r = e >> 3, c = e & 7;
        cpa(sptr(Ks + r * 72 + (c << 3)), kbase + (size_t)r * 1024 + (c << 3));
    }
    CP_COMMIT;
    for (int e = t; e < 512; e += 128) {
        int r = e >> 3, c = e & 7;
        cpa(sptr(Vs + r * 72 + (c << 3)), vbase + (size_t)r * 1024 + (c << 3));
    }
    CP_COMMIT;

    CP_WAIT(3);
    __syncthreads();
    uint32_t qf[4][4];
#pragma unroll
    for (int kc = 0; kc < 4; kc++)
        ldm4(qf[kc], sptr(Pq + (w * 16 + (lane & 15)) * 72 +
                          (kc << 4) + ((lane >> 4) << 3)));

    float O[8][4];
#pragma unroll
    for (int nt = 0; nt < 8; nt++)
#pragma unroll
        for (int i = 0; i < 4; i++) O[nt][i] = 0.f;
    float m0 = -1e30f, m1 = -1e30f, l0 = 0.f, l1 = 0.f;
    int dq0 = w * 16 + R, dq1 = dq0 + 8;

    for (int kt = 0; kt < ntiles; kt++) {
        int k0 = kt << 6;
        __half* PL = (kt & 1) ? Pp1 : Pp0;   // band cols 0-63
        __half* PH = (kt & 1) ? Pp0 : Pp1;   // band cols 64-127

        CP_WAIT(2);
        __syncthreads();

        // ---- qpos band = Q @ pos^T (64x128)
#pragma unroll
        for (int np = 0; np < 8; np++) {
            __half* base = (np < 4) ? PL : PH;
            int n0 = (np & 3) << 4;
            float qa0[4] = {0.f, 0.f, 0.f, 0.f}, qa1[4] = {0.f, 0.f, 0.f, 0.f};
#pragma unroll
            for (int kc = 0; kc < 4; kc++) {
                uint32_t bb[4];
                ldm4(bb, sptr(base + (n0 + (lane & 7) + ((lane >> 4) << 3)) * 72 +
                              (kc << 4) + (((lane >> 3) & 1) << 3)));
                mma16(qa0, qf[kc], bb[0], bb[1]);
                mma16(qa1, qf[kc], bb[2], bb[3]);
            }
            float* q0 = &Qp[dq0 * 132 + (np << 4)];
            float* q1 = &Qp[dq1 * 132 + (np << 4)];
            *(float2*)(q0 + c2)     = make_float2(qa0[0], qa0[1]);
            *(float2*)(q1 + c2)     = make_float2(qa0[2], qa0[3]);
            *(float2*)(q0 + 8 + c2) = make_float2(qa1[0], qa1[1]);
            *(float2*)(q1 + 8 + c2) = make_float2(qa1[2], qa1[3]);
        }
        __syncthreads();
        // prefetch next pos page into PL
        {
            int gr = rr0base + k0 + 128;
            for (int e = t; e < 512; e += 128) {
                int r = e >> 3, c = e & 7;
                cpa(sptr(PL + r * 72 + (c << 3)),
                    pbase + (size_t)(gr + r) * 64 + (c << 3));
            }
        }
        CP_COMMIT;

        CP_WAIT(2);
        __syncthreads();

        // ---- scores = Q @ K^T (64x64)
        float sc[8][4];
#pragma unroll
        for (int nt = 0; nt < 8; nt++)
#pragma unroll
            for (int i = 0; i < 4; i++) sc[nt][i] = 0.f;
#pragma unroll
        for (int np = 0; np < 4; np++) {
            int n0 = np << 4;
#pragma unroll
            for (int kc = 0; kc < 4; kc++) {
                uint32_t bb[4];
                ldm4(bb, sptr(Ks + (n0 + (lane & 7) + ((lane >> 4) << 3)) * 72 +
                              (kc << 4) + (((lane >> 3) & 1) << 3)));
                mma16(sc[np * 2],     qf[kc], bb[0], bb[1]);
                mma16(sc[np * 2 + 1], qf[kc], bb[2], bb[3]);
            }
        }
        __syncthreads();
        // prefetch K(kt+1) (clamped)
        {
            int kb = k0 + 64;
            for (int e = t; e < 512; e += 128) {
                int r = e >> 3, c = e & 7;
                int kr = kb + r; if (kr > Kc - 1) kr = Kc - 1;
                cpa(sptr(Ks + r * 72 + (c << 3)),
                    kbase + (size_t)kr * 1024 + (c << 3));
            }
        }
        CP_COMMIT;

        // ---- skew add + mask
#pragma unroll
        for (int nt = 0; nt < 8; nt++) {
#pragma unroll
            for (int j = 0; j < 2; j++) {
                int dk = (nt << 3) + c2 + j;
                float p0 = Qp[dq0 * 132 + dk - dq0 + 63];
                float p1 = Qp[dq1 * 132 + dk - dq1 + 63];
                bool mk0 = (k0 + dk) > (s0 + dq0 + Mc);
                bool mk1 = (k0 + dk) > (s0 + dq1 + Mc);
                sc[nt][j]     = mk0 ? -1e30f : (sc[nt][j] + p0) * 0.03125f;
                sc[nt][2 + j] = mk1 ? -1e30f : (sc[nt][2 + j] + p1) * 0.03125f;
            }
        }

        // ---- online softmax (quad-local rows); write P as fp16
        float mx0 = -1e30f, mx1 = -1e30f;
#pragma unroll
        for (int nt = 0; nt < 8; nt++) {
            mx0 = fmaxf(mx0, fmaxf(sc[nt][0], sc[nt][1]));
            mx1 = fmaxf(mx1, fmaxf(sc[nt][2], sc[nt][3]));
        }
        mx0 = fmaxf(mx0, __shfl_xor_sync(0xffffffffu, mx0, 1));
        mx0 = fmaxf(mx0, __shfl_xor_sync(0xffffffffu, mx0, 2));
        mx1 = fmaxf(mx1, __shfl_xor_sync(0xffffffffu, mx1, 1));
        mx1 = fmaxf(mx1, __shfl_xor_sync(0xffffffffu, mx1, 2));
        float mn0 = fmaxf(m0, mx0), mn1 = fmaxf(m1, mx1);
        float al0 = __expf(m0 - mn0), al1 = __expf(m1 - mn1);
        m0 = mn0; m1 = mn1;
        float su0 = 0.f, su1 = 0.f;
#pragma unroll
        for (int nt = 0; nt < 8; nt++) {
            float p0 = __expf(sc[nt][0] - mn0), p1 = __expf(sc[nt][1] - mn0);
            float p2 = __expf(sc[nt][2] - mn1), p3 = __expf(sc[nt][3] - mn1);
            su0 += p0 + p1; su1 += p2 + p3;
            int dk = (nt << 3) + c2;
            *(__half2*)(Pq + dq0 * 72 + dk) = __floats2half2_rn(p0, p1);
            *(__half2*)(Pq + dq1 * 72 + dk) = __floats2half2_rn(p2, p3);
        }
        su0 += __shfl_xor_sync(0xffffffffu, su0, 1);
        su0 += __shfl_xor_sync(0xffffffffu, su0, 2);
        su1 += __shfl_xor_sync(0xffffffffu, su1, 1);
        su1 += __shfl_xor_sync(0xffffffffu, su1, 2);
        l0 = l0 * al0 + su0; l1 = l1 * al1 + su1;
#pragma unroll
        for (int nt = 0; nt < 8; nt++) {
            O[nt][0] *= al0; O[nt][1] *= al0;
            O[nt][2] *= al1; O[nt][3] *= al1;
        }
        __syncwarp();

        CP_WAIT(2);
        __syncthreads();

        // ---- O += P @ V  (V via ldmatrix.trans)
#pragma unroll
        for (int kc = 0; kc < 4; kc++) {
            uint32_t pa[4];
            ldm4(pa, sptr(Pq + (w * 16 + (lane & 15)) * 72 +
                          (kc << 4) + ((lane >> 4) << 3)));
#pragma unroll
            for (int np = 0; np < 4; np++) {
                uint32_t bb[4];
                ldm4t(bb, sptr(Vs + ((kc << 4) + (lane & 7) + (((lane >> 3) & 1) << 3)) * 72 +
                               (np << 4) + ((lane >> 4) << 3)));
                mma16(O[np * 2],     pa, bb[0], bb[1]);
                mma16(O[np * 2 + 1], pa, bb[2], bb[3]);
            }
        }
        __syncthreads();
        // prefetch V(kt+1) (clamped)
        {
            int kb = k0 + 64;
            for (int e = t; e < 512; e += 128) {
                int r = e >> 3, c = e & 7;
                int kr = kb + r; if (kr > Kc - 1) kr = Kc - 1;
                cpa(sptr(Vs + r * 72 + (c << 3)),
                    vbase + (size_t)kr * 1024 + (c << 3));
            }
        }
        CP_COMMIT;
    }
    CP_WAIT(0);

    float i0 = 1.f / l0, i1 = 1.f / l1;
    __half* obase = g_attnh + ((size_t)(b * Sc + s0)) * 1024 + h * 64;
#pragma unroll
    for (int nt = 0; nt < 8; nt++) {
        int c = (nt << 3) + c2;
        *(__half2*)(obase + (size_t)dq0 * 1024 + c) =
            __floats2half2_rn(O[nt][0] * i0, O[nt][1] * i0);
        *(__half2*)(obase + (size_t)dq1 * 1024 + c) =
            __floats2half2_rn(O[nt][2] * i1, O[nt][3] * i1);
    }
}

// ---------------------------------------------------------------------------
extern "C" void kernel_launch(void* const* d_in, const int* in_sizes, int n_in,
                              void* d_out, int out_size) {
    const float* hidden  = (const float*)d_in[0];
    const float* pos_emb = (const float*)d_in[1];
    const float* memory  = (const float*)d_in[2];
    // d_in[3] = mask (bool) — recomputed analytically
    const float* Wq = (const float*)d_in[4];
    const float* Wk = (const float*)d_in[5];
    const float* Wv = (const float*)d_in[6];
    const float* Wo = (const float*)d_in[7];
    const float* gamma = (const float*)d_in[8];
    const float* beta  = (const float*)d_in[9];
    float* out = (float*)d_out;

    wtrans_kernel<<<dim3(32, 32, 4), dim3(32, 8)>>>(Wq, Wk, Wv, Wo);
    posconv_kernel<<<(Bc * Rc * 64 + 255) / 256, 256>>>(pos_emb);
    ln_kernel<<<Bc * Kc, 256>>>(hidden, memory, gamma, beta);

    cudaFuncSetAttribute(proj_tc, cudaFuncAttributeMaxDynamicSharedMemorySize,
                         GEMM_SMEM_BYTES);
    cudaFuncSetAttribute(out_tc, cudaFuncAttributeMaxDynamicSharedMemorySize,
                         GEMM_SMEM_BYTES);
    proj_tc<<<dim3(8, 32, 3), 256, GEMM_SMEM_BYTES>>>();

    cudaFuncSetAttribute(attn_tc, cudaFuncAttributeMaxDynamicSharedMemorySize,
                         ATTN_SMEM_BYTES);
    attn_tc<<<dim3(16, Bc * Hc), 128, ATTN_SMEM_BYTES>>>();

    out_tc<<<dim3(8, 16), 256, GEMM_SMEM_BYTES>>>(out);
}

// round 7
// speedup vs baseline: 11.0922x; 1.0673x over previous
#include <cuda_runtime.h>
#include <cuda_fp16.h>
#include <stdint.h>

#define Bc 2
#define Sc 1024
#define Mc 1024
#define Hc 16
#define Kc 2048
#define Rc 4095

// -------- scratch (static device globals; allocation is forbidden) --------
__device__ __half g_clnh[4096 * 1024];   // LN(concat) as fp16 (GEMM A operand)
__device__ float  g_hln [2048 * 1024];   // exact fp32 h_ln (residual)
__device__ __half g_qh  [2048 * 1024];
__device__ __half g_kh  [4096 * 1024];
__device__ __half g_vh  [4096 * 1024];
__device__ __half g_attnh[2048 * 1024];
__device__ __half g_wth [4 * 1024 * 1024]; // Wq,Wk,Wv,Wo transposed [n][k] fp16
__device__ __half g_posh[Bc * Rc * 64];

// ---------------------------------------------------------------------------
__device__ __forceinline__ uint32_t sptr(const void* p) {
    return (uint32_t)__cvta_generic_to_shared(p);
}
__device__ __forceinline__ void ldm4(uint32_t* r, uint32_t a) {
    asm volatile("ldmatrix.sync.aligned.m8n8.x4.shared.b16 {%0,%1,%2,%3},[%4];"
                 : "=r"(r[0]), "=r"(r[1]), "=r"(r[2]), "=r"(r[3]) : "r"(a));
}
__device__ __forceinline__ void ldm4t(uint32_t* r, uint32_t a) {
    asm volatile("ldmatrix.sync.aligned.m8n8.x4.trans.shared.b16 {%0,%1,%2,%3},[%4];"
                 : "=r"(r[0]), "=r"(r[1]), "=r"(r[2]), "=r"(r[3]) : "r"(a));
}
__device__ __forceinline__ void mma16(float* d, const uint32_t* a,
                                      uint32_t b0, uint32_t b1) {
    asm volatile(
        "mma.sync.aligned.m16n8k16.row.col.f32.f16.f16.f32 "
        "{%0,%1,%2,%3},{%4,%5,%6,%7},{%8,%9},{%0,%1,%2,%3};"
        : "+f"(d[0]), "+f"(d[1]), "+f"(d[2]), "+f"(d[3])
        : "r"(a[0]), "r"(a[1]), "r"(a[2]), "r"(a[3]), "r"(b0), "r"(b1));
}
__device__ __forceinline__ void cpa(uint32_t d, const void* s) {
    asm volatile("cp.async.cg.shared.global [%0], [%1], 16;" :: "r"(d), "l"(s));
}
#define CP_COMMIT asm volatile("cp.async.commit_group;")
#define CP_WAIT(n) asm volatile("cp.async.wait_group %0;" :: "n"(n))

// ---------------------------------------------------------------------------
__global__ void wtrans_kernel(const float* __restrict__ Wq,
                              const float* __restrict__ Wk,
                              const float* __restrict__ Wv,
                              const float* __restrict__ Wo) {
    __shared__ float tile[32][33];
    int z = blockIdx.z;
    const float* W = (z == 0) ? Wq : (z == 1) ? Wk : (z == 2) ? Wv : Wo;
    __half* Wt = g_wth + (size_t)z * 1024 * 1024;
    int bx = blockIdx.x << 5, by = blockIdx.y << 5;
    int tx = threadIdx.x, ty = threadIdx.y;
#pragma unroll
    for (int i = 0; i < 32; i += 8)
        tile[ty + i][tx] = W[(size_t)(by + ty + i) * 1024 + bx + tx];
    __syncthreads();
#pragma unroll
    for (int i = 0; i < 32; i += 8)
        Wt[(size_t)(bx + ty + i) * 1024 + by + tx] = __float2half(tile[tx][ty + i]);
}

__global__ void posconv_kernel(const float* __restrict__ p) {
    int i = blockIdx.x * 256 + threadIdx.x;
    if (i < Bc * Rc * 64) g_posh[i] = __float2half(p[i]);
}

// ---------------------------------------------------------------------------
__global__ void ln_kernel(const float* __restrict__ hidden,
                          const float* __restrict__ memory,
                          const float* __restrict__ gamma,
                          const float* __restrict__ beta) {
    int row = blockIdx.x;
    int b = row / Kc, r = row % Kc;
    const float* src = (r < Mc) ? (memory + ((size_t)b * Mc + r) * 1024)
                                : (hidden + ((size_t)b * Sc + (r - Mc)) * 1024);
    int t = threadIdx.x;
    float4 v = *(const float4*)(src + (t << 2));
    float s = v.x + v.y + v.z + v.w;
    float sq = v.x * v.x + v.y * v.y + v.z * v.z + v.w * v.w;
#pragma unroll
    for (int m = 16; m; m >>= 1) {
        s  += __shfl_xor_sync(0xffffffffu, s, m);
        sq += __shfl_xor_sync(0xffffffffu, sq, m);
    }
    __shared__ float ss[8], ssq[8];
    int w = t >> 5, l = t & 31;
    if (l == 0) { ss[w] = s; ssq[w] = sq; }
    __syncthreads();
    if (w == 0) {
        float sv  = (l < 8) ? ss[l]  : 0.f;
        float sqv = (l < 8) ? ssq[l] : 0.f;
#pragma unroll
        for (int m = 4; m; m >>= 1) {
            sv  += __shfl_xor_sync(0xffffffffu, sv, m);
            sqv += __shfl_xor_sync(0xffffffffu, sqv, m);
        }
        if (l == 0) { ss[0] = sv; ssq[0] = sqv; }
    }
    __syncthreads();
    float mean = ss[0] * (1.f / 1024.f);
    float var  = ssq[0] * (1.f / 1024.f) - mean * mean;
    float inv  = rsqrtf(var + 1e-5f);
    float4 gv = *(const float4*)(gamma + (t << 2));
    float4 bv = *(const float4*)(beta + (t << 2));
    float o0 = (v.x - mean) * inv * gv.x + bv.x;
    float o1 = (v.y - mean) * inv * gv.y + bv.y;
    float o2 = (v.z - mean) * inv * gv.z + bv.z;
    float o3 = (v.w - mean) * inv * gv.w + bv.w;
    __half2* dsth = (__half2*)(g_clnh + (size_t)row * 1024) + (t << 1);
    dsth[0] = __floats2half2_rn(o0, o1);
    dsth[1] = __floats2half2_rn(o2, o3);
    if (r >= Mc) {
        float4 ov = make_float4(o0, o1, o2, o3);
        *(float4*)(g_hln + ((size_t)b * Sc + (r - Mc)) * 1024 + (t << 2)) = ov;
    }
}

// ---------------------------------------------------------------------------
// fp16 GEMM body: C[128x128] = A[128x1024] @ Wt[128x1024]^T, BK=64,
// 3-stage ring / prefill 2 / ONE syncthreads per iter.
// ---------------------------------------------------------------------------
#define GASZ (128 * 72)
#define GSTG (2 * GASZ)
#define GEMM_SMEM_BYTES (3 * GSTG * 2)

template <int MODE>
__device__ __forceinline__ void gemm_body(const __half* __restrict__ A,
                                          const __half* __restrict__ Wt,
                                          __half* __restrict__ Ch,
                                          float* __restrict__ Cf,
                                          const float* __restrict__ res,
                                          __half* sm) {
    int t = threadIdx.x, lane = t & 31, w = t >> 5;
    int wm = (w >> 1) << 5, wn = (w & 1) << 6;

    auto load_stage = [&](int ki) {
        __half* As = sm + (ki % 3) * GSTG;
        __half* Bs = As + GASZ;
        int k0 = ki << 6;
#pragma unroll
        for (int it = 0; it < 4; it++) {
            int e = t + (it << 8);
            int r = e >> 3, c = e & 7;
            cpa(sptr(As + r * 72 + (c << 3)), A + (size_t)r * 1024 + k0 + (c << 3));
            cpa(sptr(Bs + r * 72 + (c << 3)), Wt + (size_t)r * 1024 + k0 + (c << 3));
        }
    };

    load_stage(0); CP_COMMIT;
    load_stage(1); CP_COMMIT;

    float acc[2][8][4];
#pragma unroll
    for (int mt = 0; mt < 2; mt++)
#pragma unroll
        for (int nt = 0; nt < 8; nt++)
#pragma unroll
            for (int i = 0; i < 4; i++) acc[mt][nt][i] = 0.f;

    for (int i = 0; i < 16; i++) {
        CP_WAIT(1);
        __syncthreads();
        if (i + 2 < 16) load_stage(i + 2);
        CP_COMMIT;
        __half* As = sm + (i % 3) * GSTG;
        __half* Bs = As + GASZ;
#pragma unroll
        for (int kc = 0; kc < 4; kc++) {
            uint32_t am[2][4];
#pragma unroll
            for (int mt = 0; mt < 2; mt++)
                ldm4(am[mt], sptr(As + (wm + mt * 16 + (lane & 15)) * 72 +
                                  (kc << 4) + ((lane >> 4) << 3)));
#pragma unroll
            for (int np = 0; np < 4; np++) {
                uint32_t bb[4];
                ldm4(bb, sptr(Bs + (wn + (np << 4) + (lane & 7) + ((lane >> 4) << 3)) * 72 +
                              (kc << 4) + (((lane >> 3) & 1) << 3)));
                mma16(acc[0][np * 2],     am[0], bb[0], bb[1]);
                mma16(acc[0][np * 2 + 1], am[0], bb[2], bb[3]);
                mma16(acc[1][np * 2],     am[1], bb[0], bb[1]);
                mma16(acc[1][np * 2 + 1], am[1], bb[2], bb[3]);
            }
        }
    }

    int R = lane >> 2, c2 = (lane & 3) << 1;
#pragma unroll
    for (int mt = 0; mt < 2; mt++) {
        int r0 = wm + mt * 16 + R, r1 = r0 + 8;
#pragma unroll
        for (int nt = 0; nt < 8; nt++) {
            int c = wn + (nt << 3) + c2;
            if (MODE == 0) {
                *(__half2*)(Ch + (size_t)r0 * 1024 + c) =
                    __floats2half2_rn(acc[mt][nt][0], acc[mt][nt][1]);
                *(__half2*)(Ch + (size_t)r1 * 1024 + c) =
                    __floats2half2_rn(acc[mt][nt][2], acc[mt][nt][3]);
            } else {
                const float* rs0 = res + (size_t)r0 * 1024 + c;
                const float* rs1 = res + (size_t)r1 * 1024 + c;
                Cf[(size_t)r0 * 1024 + c]     = acc[mt][nt][0] + rs0[0];
                Cf[(size_t)r0 * 1024 + c + 1] = acc[mt][nt][1] + rs0[1];
                Cf[(size_t)r1 * 1024 + c]     = acc[mt][nt][2] + rs1[0];
                Cf[(size_t)r1 * 1024 + c + 1] = acc[mt][nt][3] + rs1[1];
            }
        }
    }
}

// Fused Q/K/V projection: grid (8, 32, 3); z: 0=K, 1=V, 2=Q (y<16)
__global__ __launch_bounds__(256, 2) void proj_tc() {
    extern __shared__ __align__(16) __half smh[];
    int task = blockIdx.z, y = blockIdx.y, col0 = blockIdx.x << 7;
    const __half* A;
    const __half* Wt;
    __half* Cb;
    if (task == 0) {
        A = g_clnh + (size_t)(y << 7) * 1024;
        Wt = g_wth + (1u << 20) + (size_t)col0 * 1024;
        Cb = g_kh + (size_t)(y << 7) * 1024 + col0;
    } else if (task == 1) {
        A = g_clnh + (size_t)(y << 7) * 1024;
        Wt = g_wth + (2u << 20) + (size_t)col0 * 1024;
        Cb = g_vh + (size_t)(y << 7) * 1024 + col0;
    } else {
        if (y >= 16) return;
        int b = y >> 3, r0 = (y & 7) << 7;
        A = g_clnh + ((size_t)(b * Kc + Mc) + r0) * 1024;
        Wt = g_wth + (size_t)col0 * 1024;
        Cb = g_qh + ((size_t)(b * Sc) + r0) * 1024 + col0;
    }
    gemm_body<0>(A, Wt, Cb, nullptr, nullptr, smh);
}

// Output projection + residual: grid (8, 16)
__global__ __launch_bounds__(256, 2) void out_tc(float* __restrict__ out) {
    extern __shared__ __align__(16) __half smh[];
    int y = blockIdx.y, col0 = blockIdx.x << 7;
    const __half* A = g_attnh + (size_t)(y << 7) * 1024;
    const __half* Wt = g_wth + (3u << 20) + (size_t)col0 * 1024;
    const float* res = g_hln + (size_t)(y << 7) * 1024 + col0;
    float* Cf = out + (size_t)(y << 7) * 1024 + col0;
    gemm_body<1>(A, Wt, nullptr, Cf, res, smh);
}

// ---------------------------------------------------------------------------
// fp16 flash attention: ONE syncthreads + ONE cp.async wait per k-tile.
// K,V double-buffered; pos pages triple-buffered; 128 threads (4 warps).
// ---------------------------------------------------------------------------
#define AB_PQ 0
#define AB_K0 9216
#define AB_K1 18432
#define AB_V0 27648
#define AB_V1 36864
#define AB_P0 46080
#define AB_P1 55296
#define AB_P2 64512
#define AB_QP 73728
#define ATTN_SMEM_BYTES (AB_QP + 64 * 132 * 4)

__global__ __launch_bounds__(128) void attn_tc() {
    extern __shared__ __align__(16) char smb[];
    __half* Pq = (__half*)(smb + AB_PQ);   // Q staging, then probs P [64][72]
    __half* Kbuf[2] = {(__half*)(smb + AB_K0), (__half*)(smb + AB_K1)};
    __half* Vbuf[2] = {(__half*)(smb + AB_V0), (__half*)(smb + AB_V1)};
    __half* Pp[3] = {(__half*)(smb + AB_P0), (__half*)(smb + AB_P1),
                     (__half*)(smb + AB_P2)};
    float* Qp = (float*)(smb + AB_QP);     // qpos band fp32 [64][132]

    int t = threadIdx.x, lane = t & 31, w = t >> 5;
    int R = lane >> 2, c2 = (lane & 3) << 1;
    int qi = 15 - (int)blockIdx.x;
    int s0 = qi << 6;
    int bh = blockIdx.y, b = bh >> 4, h = bh & 15;

    const __half* qbase = g_qh + ((size_t)(b * Sc + s0)) * 1024 + h * 64;
    const __half* kbase = g_kh + ((size_t)b * Kc) * 1024 + h * 64;
    const __half* vbase = g_vh + ((size_t)b * Kc) * 1024 + h * 64;
    const __half* pbase = g_posh + (size_t)b * Rc * 64;
    int rr0base = 960 - s0;
    int ntiles = qi + 17;

    // prologue: Q, pos pages 0+1, K0, V0
    for (int e = t; e < 512; e += 128) {
        int r = e >> 3, c = e & 7;
        cpa(sptr(Pq + r * 72 + (c << 3)), qbase + (size_t)r * 1024 + (c << 3));
        cpa(sptr(Pp[0] + r * 72 + (c << 3)),
            pbase + (size_t)(rr0base + r) * 64 + (c << 3));
        cpa(sptr(Pp[1] + r * 72 + (c << 3)),
            pbase + (size_t)(rr0base + 64 + r) * 64 + (c << 3));
        cpa(sptr(Kbuf[0] + r * 72 + (c << 3)), kbase + (size_t)r * 1024 + (c << 3));
        cpa(sptr(Vbuf[0] + r * 72 + (c << 3)), vbase + (size_t)r * 1024 + (c << 3));
    }
    CP_COMMIT;
    CP_WAIT(0);
    __syncthreads();

    uint32_t qf[4][4];
#pragma unroll
    for (int kc = 0; kc < 4; kc++)
        ldm4(qf[kc], sptr(Pq + (w * 16 + (lane & 15)) * 72 +
                          (kc << 4) + ((lane >> 4) << 3)));

    float O[8][4];
#pragma unroll
    for (int nt = 0; nt < 8; nt++)
#pragma unroll
        for (int i = 0; i < 4; i++) O[nt][i] = 0.f;
    float m0 = -1e30f, m1 = -1e30f, l0 = 0.f, l1 = 0.f;
    int dq0 = w * 16 + R, dq1 = dq0 + 8;

    for (int kt = 0; kt < ntiles; kt++) {
        int k0 = kt << 6;
        __half* PL = Pp[kt % 3];
        __half* PH = Pp[(kt + 1) % 3];
        __half* Ks = Kbuf[kt & 1];
        __half* Vs = Vbuf[kt & 1];

        if (kt) { CP_WAIT(0); __syncthreads(); }

        // issue ALL prefetches for tile kt+1 (buffers not touched this tile)
        if (kt + 1 < ntiles) {
            __half* Pn = Pp[(kt + 2) % 3];
            __half* Kn = Kbuf[(kt + 1) & 1];
            __half* Vn = Vbuf[(kt + 1) & 1];
            int gp = rr0base + k0 + 128;
            int gk = k0 + 64;
            for (int e = t; e < 512; e += 128) {
                int r = e >> 3, c = e & 7;
                cpa(sptr(Pn + r * 72 + (c << 3)),
                    pbase + (size_t)(gp + r) * 64 + (c << 3));
                cpa(sptr(Kn + r * 72 + (c << 3)),
                    kbase + (size_t)(gk + r) * 1024 + (c << 3));
                cpa(sptr(Vn + r * 72 + (c << 3)),
                    vbase + (size_t)(gk + r) * 1024 + (c << 3));
            }
        }
        CP_COMMIT;

        // ---- qpos band = Q @ pos^T (64x128)
#pragma unroll
        for (int np = 0; np < 8; np++) {
            __half* base = (np < 4) ? PL : PH;
            int n0 = (np & 3) << 4;
            float qa0[4] = {0.f, 0.f, 0.f, 0.f}, qa1[4] = {0.f, 0.f, 0.f, 0.f};
#pragma unroll
            for (int kc = 0; kc < 4; kc++) {
                uint32_t bb[4];
                ldm4(bb, sptr(base + (n0 + (lane & 7) + ((lane >> 4) << 3)) * 72 +
                              (kc << 4) + (((lane >> 3) & 1) << 3)));
                mma16(qa0, qf[kc], bb[0], bb[1]);
                mma16(qa1, qf[kc], bb[2], bb[3]);
            }
            float* q0 = &Qp[dq0 * 132 + (np << 4)];
            float* q1 = &Qp[dq1 * 132 + (np << 4)];
            *(float2*)(q0 + c2)     = make_float2(qa0[0], qa0[1]);
            *(float2*)(q1 + c2)     = make_float2(qa0[2], qa0[3]);
            *(float2*)(q0 + 8 + c2) = make_float2(qa1[0], qa1[1]);
            *(float2*)(q1 + 8 + c2) = make_float2(qa1[2], qa1[3]);
        }
        __syncwarp();

        // ---- scores = Q @ K^T (64x64)
        float sc[8][4];
#pragma unroll
        for (int nt = 0; nt < 8; nt++)
#pragma unroll
            for (int i = 0; i < 4; i++) sc[nt][i] = 0.f;
#pragma unroll
        for (int np = 0; np < 4; np++) {
            int n0 = np << 4;
#pragma unroll
            for (int kc = 0; kc < 4; kc++) {
                uint32_t bb[4];
                ldm4(bb, sptr(Ks + (n0 + (lane & 7) + ((lane >> 4) << 3)) * 72 +
                              (kc << 4) + (((lane >> 3) & 1) << 3)));
                mma16(sc[np * 2],     qf[kc], bb[0], bb[1]);
                mma16(sc[np * 2 + 1], qf[kc], bb[2], bb[3]);
            }
        }

        // ---- skew add + mask
#pragma unroll
        for (int nt = 0; nt < 8; nt++) {
#pragma unroll
            for (int j = 0; j < 2; j++) {
                int dk = (nt << 3) + c2 + j;
                float p0 = Qp[dq0 * 132 + dk - dq0 + 63];
                float p1 = Qp[dq1 * 132 + dk - dq1 + 63];
                bool mk0 = (k0 + dk) > (s0 + dq0 + Mc);
                bool mk1 = (k0 + dk) > (s0 + dq1 + Mc);
                sc[nt][j]     = mk0 ? -1e30f : (sc[nt][j] + p0) * 0.03125f;
                sc[nt][2 + j] = mk1 ? -1e30f : (sc[nt][2 + j] + p1) * 0.03125f;
            }
        }

        // ---- online softmax (quad-local rows); write P as fp16
        float mx0 = -1e30f, mx1 = -1e30f;
#pragma unroll
        for (int nt = 0; nt < 8; nt++) {
            mx0 = fmaxf(mx0, fmaxf(sc[nt][0], sc[nt][1]));
            mx1 = fmaxf(mx1, fmaxf(sc[nt][2], sc[nt][3]));
        }
        mx0 = fmaxf(mx0, __shfl_xor_sync(0xffffffffu, mx0, 1));
        mx0 = fmaxf(mx0, __shfl_xor_sync(0xffffffffu, mx0, 2));
        mx1 = fmaxf(mx1, __shfl_xor_sync(0xffffffffu, mx1, 1));
        mx1 = fmaxf(mx1, __shfl_xor_sync(0xffffffffu, mx1, 2));
        float mn0 = fmaxf(m0, mx0), mn1 = fmaxf(m1, mx1);
        float al0 = __expf(m0 - mn0), al1 = __expf(m1 - mn1);
        m0 = mn0; m1 = mn1;
        float su0 = 0.f, su1 = 0.f;
#pragma unroll
        for (int nt = 0; nt < 8; nt++) {
            float p0 = __expf(sc[nt][0] - mn0), p1 = __expf(sc[nt][1] - mn0);
            float p2 = __expf(sc[nt][2] - mn1), p3 = __expf(sc[nt][3] - mn1);
            su0 += p0 + p1; su1 += p2 + p3;
            int dk = (nt << 3) + c2;
            *(__half2*)(Pq + dq0 * 72 + dk) = __floats2half2_rn(p0, p1);
            *(__half2*)(Pq + dq1 * 72 + dk) = __floats2half2_rn(p2, p3);
        }
        su0 += __shfl_xor_sync(0xffffffffu, su0, 1);
        su0 += __shfl_xor_sync(0xffffffffu, su0, 2);
        su1 += __shfl_xor_sync(0xffffffffu, su1, 1);
        su1 += __shfl_xor_sync(0xffffffffu, su1, 2);
        l0 = l0 * al0 + su0; l1 = l1 * al1 + su1;
#pragma unroll
        for (int nt = 0; nt < 8; nt++) {
            O[nt][0] *= al0; O[nt][1] *= al0;
            O[nt][2] *= al1; O[nt][3] *= al1;
        }
        __syncwarp();

        // ---- O += P @ V  (V via ldmatrix.trans; P rows are warp-private)
#pragma unroll
        for (int kc = 0; kc < 4; kc++) {
            uint32_t pa[4];
            ldm4(pa, sptr(Pq + (w * 16 + (lane & 15)) * 72 +
                          (kc << 4) + ((lane >> 4) << 3)));
#pragma unroll
            for (int np = 0; np < 4; np++) {
                uint32_t bb[4];
                ldm4t(bb, sptr(Vs + ((kc << 4) + (lane & 7) + (((lane >> 3) & 1) << 3)) * 72 +
                               (np << 4) + ((lane >> 4) << 3)));
                mma16(O[np * 2],     pa, bb[0], bb[1]);
                mma16(O[np * 2 + 1], pa, bb[2], bb[3]);
            }
        }
    }

    float i0 = 1.f / l0, i1 = 1.f / l1;
    __half* obase = g_attnh + ((size_t)(b * Sc + s0)) * 1024 + h * 64;
#pragma unroll
    for (int nt = 0; nt < 8; nt++) {
        int c = (nt << 3) + c2;
        *(__half2*)(obase + (size_t)dq0 * 1024 + c) =
            __floats2half2_rn(O[nt][0] * i0, O[nt][1] * i0);
        *(__half2*)(obase + (size_t)dq1 * 1024 + c) =
            __floats2half2_rn(O[nt][2] * i1, O[nt][3] * i1);
    }
}

// ---------------------------------------------------------------------------
extern "C" void kernel_launch(void* const* d_in, const int* in_sizes, int n_in,
                              void* d_out, int out_size) {
    const float* hidden  = (const float*)d_in[0];
    const float* pos_emb = (const float*)d_in[1];
    const float* memory  = (const float*)d_in[2];
    // d_in[3] = mask (bool) — recomputed analytically
    const float* Wq = (const float*)d_in[4];
    const float* Wk = (const float*)d_in[5];
    const float* Wv = (const float*)d_in[6];
    const float* Wo = (const float*)d_in[7];
    const float* gamma = (const float*)d_in[8];
    const float* beta  = (const float*)d_in[9];
    float* out = (float*)d_out;

    wtrans_kernel<<<dim3(32, 32, 4), dim3(32, 8)>>>(Wq, Wk, Wv, Wo);
    posconv_kernel<<<(Bc * Rc * 64 + 255) / 256, 256>>>(pos_emb);
    ln_kernel<<<Bc * Kc, 256>>>(hidden, memory, gamma, beta);

    cudaFuncSetAttribute(proj_tc, cudaFuncAttributeMaxDynamicSharedMemorySize,
                         GEMM_SMEM_BYTES);
    cudaFuncSetAttribute(out_tc, cudaFuncAttributeMaxDynamicSharedMemorySize,
                         GEMM_SMEM_BYTES);
    proj_tc<<<dim3(8, 32, 3), 256, GEMM_SMEM_BYTES>>>();

    cudaFuncSetAttribute(attn_tc, cudaFuncAttributeMaxDynamicSharedMemorySize,
                         ATTN_SMEM_BYTES);
    attn_tc<<<dim3(16, Bc * Hc), 128, ATTN_SMEM_BYTES>>>();

    out_tc<<<dim3(8, 16), 256, GEMM_SMEM_BYTES>>>(out);
}

// round 8
// speedup vs baseline: 12.6077x; 1.1366x over previous
#include <cuda_runtime.h>
#include <cuda_fp16.h>
#include <stdint.h>

#define Bc 2
#define Sc 1024
#define Mc 1024
#define Hc 16
#define Kc 2048
#define Rc 4095

// -------- scratch (static device globals; allocation is forbidden) --------
__device__ __half g_clnh[4096 * 1024];   // LN(concat) as fp16 (GEMM A operand)
__device__ float  g_hln [2048 * 1024];   // exact fp32 h_ln (residual)
__device__ __half g_qh  [2048 * 1024];
__device__ __half g_kh  [4096 * 1024];
__device__ __half g_vh  [4096 * 1024];
__device__ __half g_attnh[2048 * 1024];
__device__ __half g_wth [4 * 1024 * 1024]; // Wq,Wk,Wv,Wo transposed [n][k] fp16
__device__ __half g_posh[Bc * Rc * 64];

// ---------------------------------------------------------------------------
__device__ __forceinline__ uint32_t sptr(const void* p) {
    return (uint32_t)__cvta_generic_to_shared(p);
}
__device__ __forceinline__ void ldm4(uint32_t* r, uint32_t a) {
    asm volatile("ldmatrix.sync.aligned.m8n8.x4.shared.b16 {%0,%1,%2,%3},[%4];"
                 : "=r"(r[0]), "=r"(r[1]), "=r"(r[2]), "=r"(r[3]) : "r"(a));
}
__device__ __forceinline__ void ldm4t(uint32_t* r, uint32_t a) {
    asm volatile("ldmatrix.sync.aligned.m8n8.x4.trans.shared.b16 {%0,%1,%2,%3},[%4];"
                 : "=r"(r[0]), "=r"(r[1]), "=r"(r[2]), "=r"(r[3]) : "r"(a));
}
__device__ __forceinline__ void mma16(float* d, const uint32_t* a,
                                      uint32_t b0, uint32_t b1) {
    asm volatile(
        "mma.sync.aligned.m16n8k16.row.col.f32.f16.f16.f32 "
        "{%0,%1,%2,%3},{%4,%5,%6,%7},{%8,%9},{%0,%1,%2,%3};"
        : "+f"(d[0]), "+f"(d[1]), "+f"(d[2]), "+f"(d[3])
        : "r"(a[0]), "r"(a[1]), "r"(a[2]), "r"(a[3]), "r"(b0), "r"(b1));
}
__device__ __forceinline__ void cpa(uint32_t d, const void* s) {
    asm volatile("cp.async.cg.shared.global [%0], [%1], 16;" :: "r"(d), "l"(s));
}
#define CP_COMMIT asm volatile("cp.async.commit_group;")
#define CP_WAIT(n) asm volatile("cp.async.wait_group %0;" :: "n"(n))

// ---------------------------------------------------------------------------
// Fused pre-pass: blocks [0,4096) weight transpose; [4096,4608) pos convert;
// [4608,8704) layernorm. All 256-thread blocks, one launch.
// ---------------------------------------------------------------------------
__global__ __launch_bounds__(256) void fused_pre(
    const float* __restrict__ hidden, const float* __restrict__ memory,
    const float* __restrict__ gamma, const float* __restrict__ beta,
    const float* __restrict__ Wq, const float* __restrict__ Wk,
    const float* __restrict__ Wv, const float* __restrict__ Wo,
    const float* __restrict__ pos_emb) {
    int bid = blockIdx.x, t = threadIdx.x;

    if (bid < 4096) {  // ---- weight transpose + fp16
        __shared__ float tile[32][33];
        int z = bid >> 10, m = bid & 1023;
        const float* W = (z == 0) ? Wq : (z == 1) ? Wk : (z == 2) ? Wv : Wo;
        __half* Wt = g_wth + (size_t)z * 1024 * 1024;
        int bx = (m & 31) << 5, by = (m >> 5) << 5;
        int tx = t & 31, ty = t >> 5;
#pragma unroll
        for (int i = 0; i < 32; i += 8)
            tile[ty + i][tx] = W[(size_t)(by + ty + i) * 1024 + bx + tx];
        __syncthreads();
#pragma unroll
        for (int i = 0; i < 32; i += 8)
            Wt[(size_t)(bx + ty + i) * 1024 + by + tx] =
                __float2half(tile[tx][ty + i]);
        return;
    }
    if (bid < 4608) {  // ---- pos_emb -> fp16 (vec4)
        int i = (bid - 4096) * 256 + t;   // float4 index
        if (i < (Bc * Rc * 64) / 4) {
            float4 v = *(const float4*)(pos_emb + ((size_t)i << 2));
            __half2* d = (__half2*)(g_posh + ((size_t)i << 2));
            d[0] = __floats2half2_rn(v.x, v.y);
            d[1] = __floats2half2_rn(v.z, v.w);
        }
        return;
    }
    // ---- layernorm
    int row = bid - 4608;
    int b = row / Kc, r = row % Kc;
    const float* src = (r < Mc) ? (memory + ((size_t)b * Mc + r) * 1024)
                                : (hidden + ((size_t)b * Sc + (r - Mc)) * 1024);
    float4 v = *(const float4*)(src + (t << 2));
    float s = v.x + v.y + v.z + v.w;
    float sq = v.x * v.x + v.y * v.y + v.z * v.z + v.w * v.w;
#pragma unroll
    for (int m = 16; m; m >>= 1) {
        s  += __shfl_xor_sync(0xffffffffu, s, m);
        sq += __shfl_xor_sync(0xffffffffu, sq, m);
    }
    __shared__ float ss[8], ssq[8];
    int w = t >> 5, l = t & 31;
    if (l == 0) { ss[w] = s; ssq[w] = sq; }
    __syncthreads();
    if (w == 0) {
        float sv  = (l < 8) ? ss[l]  : 0.f;
        float sqv = (l < 8) ? ssq[l] : 0.f;
#pragma unroll
        for (int m = 4; m; m >>= 1) {
            sv  += __shfl_xor_sync(0xffffffffu, sv, m);
            sqv += __shfl_xor_sync(0xffffffffu, sqv, m);
        }
        if (l == 0) { ss[0] = sv; ssq[0] = sqv; }
    }
    __syncthreads();
    float mean = ss[0] * (1.f / 1024.f);
    float var  = ssq[0] * (1.f / 1024.f) - mean * mean;
    float inv  = rsqrtf(var + 1e-5f);
    float4 gv = *(const float4*)(gamma + (t << 2));
    float4 bv = *(const float4*)(beta + (t << 2));
    float o0 = (v.x - mean) * inv * gv.x + bv.x;
    float o1 = (v.y - mean) * inv * gv.y + bv.y;
    float o2 = (v.z - mean) * inv * gv.z + bv.z;
    float o3 = (v.w - mean) * inv * gv.w + bv.w;
    __half2* dsth = (__half2*)(g_clnh + (size_t)row * 1024) + (t << 1);
    dsth[0] = __floats2half2_rn(o0, o1);
    dsth[1] = __floats2half2_rn(o2, o3);
    if (r >= Mc) {
        *(float4*)(g_hln + ((size_t)b * Sc + (r - Mc)) * 1024 + (t << 2)) =
            make_float4(o0, o1, o2, o3);
    }
}

// ---------------------------------------------------------------------------
// fp16 GEMM body: C[128x128] = A[128x1024] @ Wt[128x1024]^T, BK=64,
// 3-stage ring / prefill 2 / ONE syncthreads per iter.
// ---------------------------------------------------------------------------
#define GASZ (128 * 72)
#define GSTG (2 * GASZ)
#define GEMM_SMEM_BYTES (3 * GSTG * 2)

template <int MODE>
__device__ __forceinline__ void gemm_body(const __half* __restrict__ A,
                                          const __half* __restrict__ Wt,
                                          __half* __restrict__ Ch,
                                          float* __restrict__ Cf,
                                          const float* __restrict__ res,
                                          __half* sm) {
    int t = threadIdx.x, lane = t & 31, w = t >> 5;
    int wm = (w >> 1) << 5, wn = (w & 1) << 6;

    auto load_stage = [&](int ki) {
        __half* As = sm + (ki % 3) * GSTG;
        __half* Bs = As + GASZ;
        int k0 = ki << 6;
#pragma unroll
        for (int it = 0; it < 4; it++) {
            int e = t + (it << 8);
            int r = e >> 3, c = e & 7;
            cpa(sptr(As + r * 72 + (c << 3)), A + (size_t)r * 1024 + k0 + (c << 3));
            cpa(sptr(Bs + r * 72 + (c << 3)), Wt + (size_t)r * 1024 + k0 + (c << 3));
        }
    };

    load_stage(0); CP_COMMIT;
    load_stage(1); CP_COMMIT;

    float acc[2][8][4];
#pragma unroll
    for (int mt = 0; mt < 2; mt++)
#pragma unroll
        for (int nt = 0; nt < 8; nt++)
#pragma unroll
            for (int i = 0; i < 4; i++) acc[mt][nt][i] = 0.f;

    for (int i = 0; i < 16; i++) {
        CP_WAIT(1);
        __syncthreads();
        if (i + 2 < 16) load_stage(i + 2);
        CP_COMMIT;
        __half* As = sm + (i % 3) * GSTG;
        __half* Bs = As + GASZ;
#pragma unroll
        for (int kc = 0; kc < 4; kc++) {
            uint32_t am[2][4];
#pragma unroll
            for (int mt = 0; mt < 2; mt++)
                ldm4(am[mt], sptr(As + (wm + mt * 16 + (lane & 15)) * 72 +
                                  (kc << 4) + ((lane >> 4) << 3)));
#pragma unroll
            for (int np = 0; np < 4; np++) {
                uint32_t bb[4];
                ldm4(bb, sptr(Bs + (wn + (np << 4) + (lane & 7) + ((lane >> 4) << 3)) * 72 +
                              (kc << 4) + (((lane >> 3) & 1) << 3)));
                mma16(acc[0][np * 2],     am[0], bb[0], bb[1]);
                mma16(acc[0][np * 2 + 1], am[0], bb[2], bb[3]);
                mma16(acc[1][np * 2],     am[1], bb[0], bb[1]);
                mma16(acc[1][np * 2 + 1], am[1], bb[2], bb[3]);
            }
        }
    }

    int R = lane >> 2, c2 = (lane & 3) << 1;
#pragma unroll
    for (int mt = 0; mt < 2; mt++) {
        int r0 = wm + mt * 16 + R, r1 = r0 + 8;
#pragma unroll
        for (int nt = 0; nt < 8; nt++) {
            int c = wn + (nt << 3) + c2;
            if (MODE == 0) {
                *(__half2*)(Ch + (size_t)r0 * 1024 + c) =
                    __floats2half2_rn(acc[mt][nt][0], acc[mt][nt][1]);
                *(__half2*)(Ch + (size_t)r1 * 1024 + c) =
                    __floats2half2_rn(acc[mt][nt][2], acc[mt][nt][3]);
            } else {
                const float* rs0 = res + (size_t)r0 * 1024 + c;
                const float* rs1 = res + (size_t)r1 * 1024 + c;
                Cf[(size_t)r0 * 1024 + c]     = acc[mt][nt][0] + rs0[0];
                Cf[(size_t)r0 * 1024 + c + 1] = acc[mt][nt][1] + rs0[1];
                Cf[(size_t)r1 * 1024 + c]     = acc[mt][nt][2] + rs1[0];
                Cf[(size_t)r1 * 1024 + c + 1] = acc[mt][nt][3] + rs1[1];
            }
        }
    }
}

// Fused Q/K/V projection: grid (8, 32, 3); z: 0=K, 1=V, 2=Q (y<16)
__global__ __launch_bounds__(256, 2) void proj_tc() {
    extern __shared__ __align__(16) __half smh[];
    int task = blockIdx.z, y = blockIdx.y, col0 = blockIdx.x << 7;
    const __half* A;
    const __half* Wt;
    __half* Cb;
    if (task == 0) {
        A = g_clnh + (size_t)(y << 7) * 1024;
        Wt = g_wth + (1u << 20) + (size_t)col0 * 1024;
        Cb = g_kh + (size_t)(y << 7) * 1024 + col0;
    } else if (task == 1) {
        A = g_clnh + (size_t)(y << 7) * 1024;
        Wt = g_wth + (2u << 20) + (size_t)col0 * 1024;
        Cb = g_vh + (size_t)(y << 7) * 1024 + col0;
    } else {
        if (y >= 16) return;
        int b = y >> 3, r0 = (y & 7) << 7;
        A = g_clnh + ((size_t)(b * Kc + Mc) + r0) * 1024;
        Wt = g_wth + (size_t)col0 * 1024;
        Cb = g_qh + ((size_t)(b * Sc) + r0) * 1024 + col0;
    }
    gemm_body<0>(A, Wt, Cb, nullptr, nullptr, smh);
}

// Output projection + residual: grid (8, 16)
__global__ __launch_bounds__(256, 2) void out_tc(float* __restrict__ out) {
    extern __shared__ __align__(16) __half smh[];
    int y = blockIdx.y, col0 = blockIdx.x << 7;
    const __half* A = g_attnh + (size_t)(y << 7) * 1024;
    const __half* Wt = g_wth + (3u << 20) + (size_t)col0 * 1024;
    const float* res = g_hln + (size_t)(y << 7) * 1024 + col0;
    float* Cf = out + (size_t)(y << 7) * 1024 + col0;
    gemm_body<1>(A, Wt, nullptr, Cf, res, smh);
}

// ---------------------------------------------------------------------------
// fp16 flash attention with qpos ring reuse: each pos page's Q@pos^T product
// is computed ONCE and reused as the low half of the next tile's band.
// K,V double-buffered; pos pages triple-buffered; ONE sync/wait per k-tile.
// ---------------------------------------------------------------------------
#define AB_PQ 0
#define AB_K0 9216
#define AB_K1 18432
#define AB_V0 27648
#define AB_V1 36864
#define AB_P0 46080
#define AB_P1 55296
#define AB_P2 64512
#define AB_QP 73728
#define ATTN_SMEM_BYTES (AB_QP + 2 * 64 * 72 * 4)

__global__ __launch_bounds__(128) void attn_tc() {
    extern __shared__ __align__(16) char smb[];
    __half* Pq = (__half*)(smb + AB_PQ);   // Q staging, then probs P [64][72]
    __half* Kbuf[2] = {(__half*)(smb + AB_K0), (__half*)(smb + AB_K1)};
    __half* Vbuf[2] = {(__half*)(smb + AB_V0), (__half*)(smb + AB_V1)};
    __half* Pp[3] = {(__half*)(smb + AB_P0), (__half*)(smb + AB_P1),
                     (__half*)(smb + AB_P2)};
    float* Qpr = (float*)(smb + AB_QP);    // qpos ring: 2 x [64][72] fp32

    int t = threadIdx.x, lane = t & 31, w = t >> 5;
    int R = lane >> 2, c2 = (lane & 3) << 1;
    int qi = 15 - (int)blockIdx.x;
    int s0 = qi << 6;
    int bh = blockIdx.y, b = bh >> 4, h = bh & 15;

    const __half* qbase = g_qh + ((size_t)(b * Sc + s0)) * 1024 + h * 64;
    const __half* kbase = g_kh + ((size_t)b * Kc) * 1024 + h * 64;
    const __half* vbase = g_vh + ((size_t)b * Kc) * 1024 + h * 64;
    const __half* pbase = g_posh + (size_t)b * Rc * 64;
    int rr0base = 960 - s0;
    int ntiles = qi + 17;
    int dq0 = w * 16 + R, dq1 = dq0 + 8;

    // prologue loads: Q, pos pages 0+1, K0, V0
    for (int e = t; e < 512; e += 128) {
        int r = e >> 3, c = e & 7;
        cpa(sptr(Pq + r * 72 + (c << 3)), qbase + (size_t)r * 1024 + (c << 3));
        cpa(sptr(Pp[0] + r * 72 + (c << 3)),
            pbase + (size_t)(rr0base + r) * 64 + (c << 3));
        cpa(sptr(Pp[1] + r * 72 + (c << 3)),
            pbase + (size_t)(rr0base + 64 + r) * 64 + (c << 3));
        cpa(sptr(Kbuf[0] + r * 72 + (c << 3)), kbase + (size_t)r * 1024 + (c << 3));
        cpa(sptr(Vbuf[0] + r * 72 + (c << 3)), vbase + (size_t)r * 1024 + (c << 3));
    }
    CP_COMMIT;
    CP_WAIT(0);
    __syncthreads();

    uint32_t qf[4][4];
#pragma unroll
    for (int kc = 0; kc < 4; kc++)
        ldm4(qf[kc], sptr(Pq + (w * 16 + (lane & 15)) * 72 +
                          (kc << 4) + ((lane >> 4) << 3)));

    // qpos helper: compute Q @ pos_page^T (64x64) into ring slot
    auto qpos_page = [&](__half* page, float* dst) {
#pragma unroll
        for (int np = 0; np < 4; np++) {
            float qa0[4] = {0.f, 0.f, 0.f, 0.f}, qa1[4] = {0.f, 0.f, 0.f, 0.f};
#pragma unroll
            for (int kc = 0; kc < 4; kc++) {
                uint32_t bb[4];
                ldm4(bb, sptr(page + ((np << 4) + (lane & 7) + ((lane >> 4) << 3)) * 72 +
                              (kc << 4) + (((lane >> 3) & 1) << 3)));
                mma16(qa0, qf[kc], bb[0], bb[1]);
                mma16(qa1, qf[kc], bb[2], bb[3]);
            }
            float* q0 = dst + dq0 * 72 + (np << 4);
            float* q1 = dst + dq1 * 72 + (np << 4);
            *(float2*)(q0 + c2)     = make_float2(qa0[0], qa0[1]);
            *(float2*)(q1 + c2)     = make_float2(qa0[2], qa0[3]);
            *(float2*)(q0 + 8 + c2) = make_float2(qa1[0], qa1[1]);
            *(float2*)(q1 + 8 + c2) = make_float2(qa1[2], qa1[3]);
        }
    };

    // prologue qpos: page 0 -> ring slot 0
    qpos_page(Pp[0], Qpr);

    float O[8][4];
#pragma unroll
    for (int nt = 0; nt < 8; nt++)
#pragma unroll
        for (int i = 0; i < 4; i++) O[nt][i] = 0.f;
    float m0 = -1e30f, m1 = -1e30f, l0 = 0.f, l1 = 0.f;

    for (int kt = 0; kt < ntiles; kt++) {
        int k0 = kt << 6;
        float* QpL = Qpr + (kt & 1) * (64 * 72);
        float* QpH = Qpr + ((kt + 1) & 1) * (64 * 72);
        __half* Ks = Kbuf[kt & 1];
        __half* Vs = Vbuf[kt & 1];

        if (kt) { CP_WAIT(0); __syncthreads(); }

        // prefetch tile kt+1: pos page kt+2, K(kt+1), V(kt+1)
        if (kt + 1 < ntiles) {
            __half* Pn = Pp[(kt + 2) % 3];
            __half* Kn = Kbuf[(kt + 1) & 1];
            __half* Vn = Vbuf[(kt + 1) & 1];
            int gp = rr0base + k0 + 128;
            int gk = k0 + 64;
            for (int e = t; e < 512; e += 128) {
                int r = e >> 3, c = e & 7;
                cpa(sptr(Pn + r * 72 + (c << 3)),
                    pbase + (size_t)(gp + r) * 64 + (c << 3));
                cpa(sptr(Kn + r * 72 + (c << 3)),
                    kbase + (size_t)(gk + r) * 1024 + (c << 3));
                cpa(sptr(Vn + r * 72 + (c << 3)),
                    vbase + (size_t)(gk + r) * 1024 + (c << 3));
            }
        }
        CP_COMMIT;

        // ---- fresh qpos: page kt+1 -> ring slot (kt+1)&1 (becomes high half)
        qpos_page(Pp[(kt + 1) % 3], QpH);
        __syncwarp();

        // ---- scores = Q @ K^T (64x64)
        float sc[8][4];
#pragma unroll
        for (int nt = 0; nt < 8; nt++)
#pragma unroll
            for (int i = 0; i < 4; i++) sc[nt][i] = 0.f;
#pragma unroll
        for (int np = 0; np < 4; np++) {
            int n0 = np << 4;
#pragma unroll
            for (int kc = 0; kc < 4; kc++) {
                uint32_t bb[4];
                ldm4(bb, sptr(Ks + (n0 + (lane & 7) + ((lane >> 4) << 3)) * 72 +
                              (kc << 4) + (((lane >> 3) & 1) << 3)));
                mma16(sc[np * 2],     qf[kc], bb[0], bb[1]);
                mma16(sc[np * 2 + 1], qf[kc], bb[2], bb[3]);
            }
        }

        // ---- skew add + mask (band col j = dk - dq + 63; L page j<64)
#pragma unroll
        for (int nt = 0; nt < 8; nt++) {
#pragma unroll
            for (int j = 0; j < 2; j++) {
                int dk = (nt << 3) + c2 + j;
                int j0 = dk - dq0 + 63, j1 = dk - dq1 + 63;
                float p0 = (j0 < 64) ? QpL[dq0 * 72 + j0] : QpH[dq0 * 72 + j0 - 64];
                float p1 = (j1 < 64) ? QpL[dq1 * 72 + j1] : QpH[dq1 * 72 + j1 - 64];
                bool mk0 = (k0 + dk) > (s0 + dq0 + Mc);
                bool mk1 = (k0 + dk) > (s0 + dq1 + Mc);
                sc[nt][j]     = mk0 ? -1e30f : (sc[nt][j] + p0) * 0.03125f;
                sc[nt][2 + j] = mk1 ? -1e30f : (sc[nt][2 + j] + p1) * 0.03125f;
            }
        }

        // ---- online softmax (quad-local rows); write P as fp16
        float mx0 = -1e30f, mx1 = -1e30f;
#pragma unroll
        for (int nt = 0; nt < 8; nt++) {
            mx0 = fmaxf(mx0, fmaxf(sc[nt][0], sc[nt][1]));
            mx1 = fmaxf(mx1, fmaxf(sc[nt][2], sc[nt][3]));
        }
        mx0 = fmaxf(mx0, __shfl_xor_sync(0xffffffffu, mx0, 1));
        mx0 = fmaxf(mx0, __shfl_xor_sync(0xffffffffu, mx0, 2));
        mx1 = fmaxf(mx1, __shfl_xor_sync(0xffffffffu, mx1, 1));
        mx1 = fmaxf(mx1, __shfl_xor_sync(0xffffffffu, mx1, 2));
        float mn0 = fmaxf(m0, mx0), mn1 = fmaxf(m1, mx1);
        float al0 = __expf(m0 - mn0), al1 = __expf(m1 - mn1);
        m0 = mn0; m1 = mn1;
        float su0 = 0.f, su1 = 0.f;
#pragma unroll
        for (int nt = 0; nt < 8; nt++) {
            float p0 = __expf(sc[nt][0] - mn0), p1 = __expf(sc[nt][1] - mn0);
            float p2 = __expf(sc[nt][2] - mn1), p3 = __expf(sc[nt][3] - mn1);
            su0 += p0 + p1; su1 += p2 + p3;
            int dk = (nt << 3) + c2;
            *(__half2*)(Pq + dq0 * 72 + dk) = __floats2half2_rn(p0, p1);
            *(__half2*)(Pq + dq1 * 72 + dk) = __floats2half2_rn(p2, p3);
        }
        su0 += __shfl_xor_sync(0xffffffffu, su0, 1);
        su0 += __shfl_xor_sync(0xffffffffu, su0, 2);
        su1 += __shfl_xor_sync(0xffffffffu, su1, 1);
        su1 += __shfl_xor_sync(0xffffffffu, su1, 2);
        l0 = l0 * al0 + su0; l1 = l1 * al1 + su1;
#pragma unroll
        for (int nt = 0; nt < 8; nt++) {
            O[nt][0] *= al0; O[nt][1] *= al0;
            O[nt][2] *= al1; O[nt][3] *= al1;
        }
        __syncwarp();

        // ---- O += P @ V  (V via ldmatrix.trans; P rows are warp-private)
#pragma unroll
        for (int kc = 0; kc < 4; kc++) {
            uint32_t pa[4];
            ldm4(pa, sptr(Pq + (w * 16 + (lane & 15)) * 72 +
                          (kc << 4) + ((lane >> 4) << 3)));
#pragma unroll
            for (int np = 0; np < 4; np++) {
                uint32_t bb[4];
                ldm4t(bb, sptr(Vs + ((kc << 4) + (lane & 7) + (((lane >> 3) & 1) << 3)) * 72 +
                               (np << 4) + ((lane >> 4) << 3)));
                mma16(O[np * 2],     pa, bb[0], bb[1]);
                mma16(O[np * 2 + 1], pa, bb[2], bb[3]);
            }
        }
    }

    float i0 = 1.f / l0, i1 = 1.f / l1;
    __half* obase = g_attnh + ((size_t)(b * Sc + s0)) * 1024 + h * 64;
#pragma unroll
    for (int nt = 0; nt < 8; nt++) {
        int c = (nt << 3) + c2;
        *(__half2*)(obase + (size_t)dq0 * 1024 + c) =
            __floats2half2_rn(O[nt][0] * i0, O[nt][1] * i0);
        *(__half2*)(obase + (size_t)dq1 * 1024 + c) =
            __floats2half2_rn(O[nt][2] * i1, O[nt][3] * i1);
    }
}

// ---------------------------------------------------------------------------
extern "C" void kernel_launch(void* const* d_in, const int* in_sizes, int n_in,
                              void* d_out, int out_size) {
    const float* hidden  = (const float*)d_in[0];
    const float* pos_emb = (const float*)d_in[1];
    const float* memory  = (const float*)d_in[2];
    // d_in[3] = mask (bool) — recomputed analytically
    const float* Wq = (const float*)d_in[4];
    const float* Wk = (const float*)d_in[5];
    const float* Wv = (const float*)d_in[6];
    const float* Wo = (const float*)d_in[7];
    const float* gamma = (const float*)d_in[8];
    const float* beta  = (const float*)d_in[9];
    float* out = (float*)d_out;

    fused_pre<<<8704, 256>>>(hidden, memory, gamma, beta, Wq, Wk, Wv, Wo,
                             pos_emb);

    cudaFuncSetAttribute(proj_tc, cudaFuncAttributeMaxDynamicSharedMemorySize,
                         GEMM_SMEM_BYTES);
    cudaFuncSetAttribute(out_tc, cudaFuncAttributeMaxDynamicSharedMemorySize,
                         GEMM_SMEM_BYTES);
    proj_tc<<<dim3(8, 32, 3), 256, GEMM_SMEM_BYTES>>>();

    cudaFuncSetAttribute(attn_tc, cudaFuncAttributeMaxDynamicSharedMemorySize,
                         ATTN_SMEM_BYTES);
    attn_tc<<<dim3(16, Bc * Hc), 128, ATTN_SMEM_BYTES>>>();

    out_tc<<<dim3(8, 16), 256, GEMM_SMEM_BYTES>>>(out);
}